// round 13
// baseline (speedup 1.0000x reference)
#include <cuda_runtime.h>
#include <cuda_fp16.h>
#include <cuda_bf16.h>

#define NN 50000
#define NE 800000
#define IND 128
#define OUTD 64
#define HEADS 4
#define HD 256      // HEADS*OUTD
#define HID 256
#define MOUT 128
#define NBLK 49     // ceil(NN/1024)

// ---- scratch (device globals: allocation-free) ----
__device__ __half g_h[(size_t)NN * HD];       // transformed features (fp16)
__device__ __half g_act[(size_t)NN * HD];     // relu(num/den): GEMM2 input (fp16)
__device__ __half g_hidden[(size_t)NN * HID]; // MLP hidden (fp16)
__device__ float g_s_src[NN * HEADS];
__device__ float g_s_dst[NN * HEADS];
// weights: fp16, pre-transposed to [N][K] (col-major B for m16n8k16)
__device__ __half g_WcT[HD * IND];
__device__ __half g_W1T[HID * HD];
__device__ __half g_W2T[MOUT * HID];
// CSR-by-dst build. Self-resetting invariant: g_cnt zeroed by scatter (prev run),
// g_flag zeroed by its unique reader, g_ticket zeroed by last scan block.
// Static zero-init covers the very first run.
__device__ int g_cnt[NN];
__device__ int g_off[NN + 1];
__device__ int g_pos[NN];
__device__ int g_esrc[NE];
__device__ int g_ticket;
__device__ volatile int g_flag[NBLK];

// ---- pack weights (fp16, transposed) + dst histogram (g_cnt pre-zeroed) ----
__global__ void pack_hist_kernel(const float* __restrict__ Wn,
                                 const float* __restrict__ W1,
                                 const float* __restrict__ W2,
                                 const int* __restrict__ dst) {
    int i = blockIdx.x * blockDim.x + threadIdx.x;
    if (i < HD * IND) {          // WcT[j][c] = Wn[h, c, d], j = h*64+d
        int j = i / IND;
        int c = i % IND;
        int h = j >> 6;
        int d = j & 63;
        g_WcT[i] = __float2half_rn(Wn[h * (IND * OUTD) + c * OUTD + d]);
    }
    if (i < HID * HD) {          // W1T[n][k] = W1[k][n]
        int n = i / HD;
        int k = i % HD;
        g_W1T[i] = __float2half_rn(W1[k * HID + n]);
    }
    if (i < MOUT * HID) {        // W2T[n][k] = W2[k][n]
        int n = i / HID;
        int k = i % HID;
        g_W2T[i] = __float2half_rn(W2[k * MOUT + n]);
    }
    if (i < NE) atomicAdd(&g_cnt[dst[i]], 1);
}

// ---- single-pass chained scan (decoupled lookback, ticket-ordered) ----
__global__ void scan_chain_kernel() {
    __shared__ int wsum[32];
    __shared__ int s_bid, s_prev;
    int tid = threadIdx.x;           // 1024
    int lane = tid & 31;
    int wid = tid >> 5;
    if (tid == 0) s_bid = atomicAdd(&g_ticket, 1);
    __syncthreads();
    int bid = s_bid;

    int i = bid * 1024 + tid;
    int v = (i < NN) ? g_cnt[i] : 0;
    int x = v;
#pragma unroll
    for (int o = 1; o < 32; o <<= 1) {
        int t = __shfl_up_sync(0xffffffffu, x, o);
        if (lane >= o) x += t;
    }
    if (lane == 31) wsum[wid] = x;
    __syncthreads();
    if (wid == 0) {
        int s = wsum[lane];
#pragma unroll
        for (int o = 1; o < 32; o <<= 1) {
            int t = __shfl_up_sync(0xffffffffu, s, o);
            if (lane >= o) s += t;
        }
        wsum[lane] = s;
    }
    __syncthreads();
    int incl = x + ((wid > 0) ? wsum[wid - 1] : 0);
    int total = wsum[31];

    if (tid == 0) {
        int prev = 0;
        if (bid > 0) {
            int f;
            do { f = g_flag[bid - 1]; } while (f == 0);
            prev = f - 1;                 // flag carries inclusive prefix + 1
            g_flag[bid - 1] = 0;          // reset for next replay (unique reader)
        }
        if (bid < NBLK - 1) g_flag[bid] = prev + total + 1;  // last block: no reader
        s_prev = prev;
    }
    __syncthreads();
    int excl = incl - v + s_prev;
    if (i < NN) { g_off[i] = excl; g_pos[i] = excl; }
    if (bid == NBLK - 1 && tid == 0) { g_off[NN] = NE; g_ticket = 0; }
}

// ---- scatter edges into dst-grouped order; also reset g_cnt for next replay ----
__global__ void scatter_kernel(const int* __restrict__ src, const int* __restrict__ dst) {
    int i = blockIdx.x * blockDim.x + threadIdx.x;
    if (i < NN) g_cnt[i] = 0;
    if (i < NE) {
        int d = dst[i];
        int p = atomicAdd(&g_pos[d], 1);
        g_esrc[p] = src[i];
    }
}

__device__ __forceinline__ void mma_f16(float& c0, float& c1, float& c2, float& c3,
                                        unsigned a0, unsigned a1, unsigned a2, unsigned a3,
                                        unsigned b0, unsigned b1) {
    asm volatile("mma.sync.aligned.m16n8k16.row.col.f32.f16.f16.f32 "
                 "{%0,%1,%2,%3}, {%4,%5,%6,%7}, {%8,%9}, {%0,%1,%2,%3};"
                 : "+f"(c0), "+f"(c1), "+f"(c2), "+f"(c3)
                 : "r"(a0), "r"(a1), "r"(a2), "r"(a3), "r"(b0), "r"(b1));
}

// ---- fp16 tensor-core GEMM, single-buffer smem + register prefetch (R11 loop) ----
// C[M,N] = act(A @ BT^T + bias). BT is fp16 [N][K] (pre-transposed).
// EPI 0: none. 1: +bias, relu. 2: +bias.
// SCORE 1: emit g_s_src/g_s_dst from fp32 accumulators (GEMM1 only).
// AHALF: A is fp16 (else fp32). CHALF: C is fp16 (else fp32).
template<int EPI, int SCORE, int AHALF, int CHALF>
__global__ void __launch_bounds__(256, 2)
gemm_f16_kernel(const void* __restrict__ Av, const __half* __restrict__ BT,
                const float* __restrict__ bias,
                const float* __restrict__ asrc, const float* __restrict__ adst,
                void* __restrict__ Cv, int M, int N, int K)
{
    const int BM = 128, BN = 128, BK = 32;
    const int PAD = 40;                 // halves per row (80B): conflict-free frag LDS
    __shared__ __half As[BM * PAD];     // [m][k]
    __shared__ __half Bs[BN * PAD];     // [n][k]

    const float*  Af = (const float*)Av;
    const __half* Ah = (const __half*)Av;
    float*  Cf = (float*)Cv;
    __half* Ch = (__half*)Cv;

    int tid = threadIdx.x;
    int wid = tid >> 5;
    int lane = tid & 31;
    int grp = lane >> 2;
    int tig = lane & 3;

    int warp_m = (wid & 3) * 32;
    int warp_n = (wid >> 2) * 64;

    int m0 = blockIdx.x * BM;
    int n0 = blockIdx.y * BN;

    float4 ra[4];
    uint4 rah[2];
    uint4 rb[2];

    // prologue loads (k0 = 0)
    if (AHALF) {
#pragma unroll
        for (int j = 0; j < 2; j++) {
            int i = tid + j * 256;
            int row = i >> 2;
            int c8 = (i & 3) * 8;
            int gm = m0 + row;
            rah[j] = make_uint4(0u, 0u, 0u, 0u);
            if (gm < M) rah[j] = *(const uint4*)(Ah + (size_t)gm * K + c8);
        }
    } else {
#pragma unroll
        for (int j = 0; j < 4; j++) {
            int i = tid + j * 256;
            int row = i >> 3;
            int c4 = (i & 7) * 4;
            int gm = m0 + row;
            ra[j] = make_float4(0.f, 0.f, 0.f, 0.f);
            if (gm < M) ra[j] = *(const float4*)(Af + (size_t)gm * K + c4);
        }
    }
#pragma unroll
    for (int j = 0; j < 2; j++) {
        int i = tid + j * 256;
        int n = i >> 2;
        int c8 = (i & 3) * 8;
        rb[j] = *(const uint4*)(BT + (size_t)(n0 + n) * K + c8);
    }

    float acc[2][8][4];
#pragma unroll
    for (int i = 0; i < 2; i++)
#pragma unroll
        for (int j = 0; j < 8; j++)
#pragma unroll
            for (int q = 0; q < 4; q++) acc[i][j][q] = 0.0f;

    for (int k0 = 0; k0 < K; k0 += BK) {
        // store current tile to smem
        if (AHALF) {
#pragma unroll
            for (int j = 0; j < 2; j++) {
                int i = tid + j * 256;
                int row = i >> 2;
                int c8 = (i & 3) * 8;
                *(uint4*)&As[row * PAD + c8] = rah[j];
            }
        } else {
#pragma unroll
            for (int j = 0; j < 4; j++) {
                int i = tid + j * 256;
                int row = i >> 3;
                int c4 = (i & 7) * 4;
                __half2* p = (__half2*)&As[row * PAD + c4];
                p[0] = __floats2half2_rn(ra[j].x, ra[j].y);
                p[1] = __floats2half2_rn(ra[j].z, ra[j].w);
            }
        }
#pragma unroll
        for (int j = 0; j < 2; j++) {
            int i = tid + j * 256;
            int n = i >> 2;
            int c8 = (i & 3) * 8;
            *(uint4*)&Bs[n * PAD + c8] = rb[j];
        }
        __syncthreads();

        // prefetch next tile while computing
        int kn = k0 + BK;
        if (kn < K) {
            if (AHALF) {
#pragma unroll
                for (int j = 0; j < 2; j++) {
                    int i = tid + j * 256;
                    int row = i >> 2;
                    int c8 = (i & 3) * 8;
                    int gm = m0 + row;
                    rah[j] = make_uint4(0u, 0u, 0u, 0u);
                    if (gm < M) rah[j] = *(const uint4*)(Ah + (size_t)gm * K + kn + c8);
                }
            } else {
#pragma unroll
                for (int j = 0; j < 4; j++) {
                    int i = tid + j * 256;
                    int row = i >> 3;
                    int c4 = (i & 7) * 4;
                    int gm = m0 + row;
                    ra[j] = make_float4(0.f, 0.f, 0.f, 0.f);
                    if (gm < M) ra[j] = *(const float4*)(Af + (size_t)gm * K + kn + c4);
                }
            }
#pragma unroll
            for (int j = 0; j < 2; j++) {
                int i = tid + j * 256;
                int n = i >> 2;
                int c8 = (i & 3) * 8;
                rb[j] = *(const uint4*)(BT + (size_t)(n0 + n) * K + kn + c8);
            }
        }

        // compute: 2 k-steps of m16n8k16
#pragma unroll
        for (int kk = 0; kk < BK; kk += 16) {
            unsigned af[2][4];
#pragma unroll
            for (int mt = 0; mt < 2; mt++) {
                int r0 = warp_m + mt * 16 + grp;
                af[mt][0] = *(const unsigned*)&As[(r0)     * PAD + kk + 2 * tig];
                af[mt][1] = *(const unsigned*)&As[(r0 + 8) * PAD + kk + 2 * tig];
                af[mt][2] = *(const unsigned*)&As[(r0)     * PAD + kk + 2 * tig + 8];
                af[mt][3] = *(const unsigned*)&As[(r0 + 8) * PAD + kk + 2 * tig + 8];
            }
#pragma unroll
            for (int nt = 0; nt < 8; nt++) {
                int nb = warp_n + nt * 8 + grp;
                unsigned b0 = *(const unsigned*)&Bs[nb * PAD + kk + 2 * tig];
                unsigned b1 = *(const unsigned*)&Bs[nb * PAD + kk + 2 * tig + 8];
#pragma unroll
                for (int mt = 0; mt < 2; mt++)
                    mma_f16(acc[mt][nt][0], acc[mt][nt][1], acc[mt][nt][2], acc[mt][nt][3],
                            af[mt][0], af[mt][1], af[mt][2], af[mt][3], b0, b1);
            }
        }
        __syncthreads();
    }

    // --- epilogue ---
    int head = (n0 + warp_n) >> 6;   // warp tile spans exactly one head
#pragma unroll
    for (int mt = 0; mt < 2; mt++) {
#pragma unroll
        for (int half = 0; half < 2; half++) {
            int gm = m0 + warp_m + mt * 16 + grp + half * 8;
            if (gm >= M) continue;
            float ss = 0.0f, sd = 0.0f;
#pragma unroll
            for (int nt = 0; nt < 8; nt++) {
                int gn = n0 + warp_n + nt * 8 + tig * 2;
                float v0 = acc[mt][nt][half * 2 + 0];
                float v1 = acc[mt][nt][half * 2 + 1];
                if (EPI >= 1) { v0 += bias[gn]; v1 += bias[gn + 1]; }
                if (EPI == 1) { v0 = fmaxf(v0, 0.0f); v1 = fmaxf(v1, 0.0f); }
                if (SCORE) {
                    float2 a2 = *(const float2*)(asrc + gn);
                    float2 d2 = *(const float2*)(adst + gn);
                    ss += v0 * a2.x + v1 * a2.y;
                    sd += v0 * d2.x + v1 * d2.y;
                }
                if (CHALF) {
                    *(__half2*)(Ch + (size_t)gm * N + gn) = __floats2half2_rn(v0, v1);
                } else {
                    *(float2*)(Cf + (size_t)gm * N + gn) = make_float2(v0, v1);
                }
            }
            if (SCORE) {
                ss += __shfl_down_sync(0xffffffffu, ss, 2);
                ss += __shfl_down_sync(0xffffffffu, ss, 1);
                sd += __shfl_down_sync(0xffffffffu, sd, 2);
                sd += __shfl_down_sync(0xffffffffu, sd, 1);
                if (tig == 0) {
                    g_s_src[gm * HEADS + head] = ss;
                    g_s_dst[gm * HEADS + head] = sd;
                }
            }
        }
    }
}

// ---- gather: one warp per dst node; batched scores (8 edges at once) +
//      depth-1 pipelined row loads; fp16 h rows, fp32 accumulation ----
__global__ void gather_kernel() {
    int gw = (blockIdx.x * blockDim.x + threadIdx.x) >> 5;
    int lane = threadIdx.x & 31;
    if (gw >= NN) return;

    int beg = g_off[gw];
    int end = g_off[gw + 1];
    int head = lane >> 3;            // head this lane's row-slice belongs to
    int hq = lane & 3;               // head this lane scores

    float sdst_h = g_s_dst[gw * HEADS + hq];

    float acc[8];
#pragma unroll
    for (int q = 0; q < 8; q++) acc[q] = 0.0f;
    float denp = 0.0f;               // partial den for head hq (lanes hq,hq+4,...)

    for (int chunk = beg; chunk < end; chunk += 32) {
        int idx = chunk + lane;
        int myE = (idx < end) ? g_esrc[idx] : 0;
        int cnt = min(32, end - chunk);
        for (int g = 0; g < cnt; g += 8) {
            // --- scores for 8 edges in parallel: lane handles edge g+(lane/4), head hq
            int ei = g + (lane >> 2);
            int se = __shfl_sync(0xffffffffu, myE, ei);
            float ex = 0.0f;
            if (ei < cnt) {
                float e = g_s_src[se * HEADS + hq] + sdst_h;
                e = e > 0.0f ? e : 0.2f * e;
                ex = __expf(e);
                denp += ex;
            }
            // --- weighted rows, depth-1 prefetch
            int lim = min(8, cnt - g);
            int s0 = __shfl_sync(0xffffffffu, myE, g);
            uint4 v = ((const uint4*)(g_h + (size_t)s0 * HD))[lane];
            for (int j = 0; j < lim; j++) {
                uint4 vc = v;
                if (j + 1 < lim) {
                    int sn = __shfl_sync(0xffffffffu, myE, g + j + 1);
                    v = ((const uint4*)(g_h + (size_t)sn * HD))[lane];
                }
                float exh = __shfl_sync(0xffffffffu, ex, j * 4 + head);
                const __half2* hv = (const __half2*)&vc;
#pragma unroll
                for (int q = 0; q < 4; q++) {
                    float2 f = __half22float2(hv[q]);
                    acc[q * 2]     = fmaf(exh, f.x, acc[q * 2]);
                    acc[q * 2 + 1] = fmaf(exh, f.y, acc[q * 2 + 1]);
                }
            }
        }
    }

    // reduce den partials: lanes congruent mod 4 -> lanes 0..3 hold heads 0..3
    denp += __shfl_down_sync(0xffffffffu, denp, 16);
    denp += __shfl_down_sync(0xffffffffu, denp, 8);
    denp += __shfl_down_sync(0xffffffffu, denp, 4);
    float denh = __shfl_sync(0xffffffffu, denp, head);
    float inv = denh > 0.0f ? 1.0f / denh : 0.0f;

    uint4 outv;
    __half2* ov = (__half2*)&outv;
#pragma unroll
    for (int q = 0; q < 4; q++) {
        float x = fmaxf(acc[q * 2]     * inv, 0.0f);
        float y = fmaxf(acc[q * 2 + 1] * inv, 0.0f);
        ov[q] = __floats2half2_rn(x, y);
    }
    ((uint4*)(g_act + (size_t)gw * HD))[lane] = outv;
}

extern "C" void kernel_launch(void* const* d_in, const int* in_sizes, int n_in,
                              void* d_out, int out_size) {
    const float* node_emb = (const float*)d_in[0];
    const int*   src      = (const int*)d_in[1];
    const int*   dst      = (const int*)d_in[2];
    const float* W_n      = (const float*)d_in[3];
    const float* a_src    = (const float*)d_in[4];
    const float* a_dst    = (const float*)d_in[5];
    const float* W1       = (const float*)d_in[6];
    const float* b1       = (const float*)d_in[7];
    const float* W2       = (const float*)d_in[8];
    const float* b2       = (const float*)d_in[9];
    float* out = (float*)d_out;

    __half* h_ptr;   cudaGetSymbolAddress((void**)&h_ptr, g_h);
    __half* act_ptr; cudaGetSymbolAddress((void**)&act_ptr, g_act);
    __half* hid_ptr; cudaGetSymbolAddress((void**)&hid_ptr, g_hidden);
    __half* wcT_ptr; cudaGetSymbolAddress((void**)&wcT_ptr, g_WcT);
    __half* w1T_ptr; cudaGetSymbolAddress((void**)&w1T_ptr, g_W1T);
    __half* w2T_ptr; cudaGetSymbolAddress((void**)&w2T_ptr, g_W2T);

    // 1. pack weights + dst histogram (g_cnt was zeroed by prev scatter / static init)
    pack_hist_kernel<<<(NE + 255) / 256, 256>>>(W_n, W1, W2, dst);

    // 2. CSR offsets + scatter (scan/scatter self-reset their state)
    scan_chain_kernel<<<NBLK, 1024>>>();
    scatter_kernel<<<(NE + 255) / 256, 256>>>(src, dst);

    // 3. GEMM1 + fused scores: h(fp16) = X @ Wc ; s_src/s_dst(fp32)
    {
        dim3 grid((NN + 127) / 128, HD / 128);
        gemm_f16_kernel<0, 1, 0, 1><<<grid, 256>>>(node_emb, wcT_ptr, nullptr,
                                                   a_src, a_dst, h_ptr, NN, HD, IND);
    }

    // 4. gather: per-dst softmax aggregation -> g_act (fp16, normalized + relu)
    gather_kernel<<<(NN * 32 + 255) / 256, 256>>>();

    // 5. GEMM2: hidden(fp16) = relu( act(fp16) @ W1 + b1 )
    {
        dim3 grid((NN + 127) / 128, HID / 128);
        gemm_f16_kernel<1, 0, 1, 1><<<grid, 256>>>(act_ptr, w1T_ptr, b1,
                                                   nullptr, nullptr, hid_ptr, NN, HID, HD);
    }

    // 6. GEMM3: out(fp32) = hidden(fp16) @ W2 + b2
    {
        dim3 grid((NN + 127) / 128, MOUT / 128);
        gemm_f16_kernel<2, 0, 1, 0><<<grid, 256>>>(hid_ptr, w2T_ptr, b2,
                                                   nullptr, nullptr, out, NN, MOUT, HID);
    }
}

// round 14
// speedup vs baseline: 1.1844x; 1.1844x over previous
#include <cuda_runtime.h>
#include <cuda_fp16.h>
#include <cuda_bf16.h>

#define NN 50000
#define NE 800000
#define IND 128
#define OUTD 64
#define HEADS 4
#define HD 256      // HEADS*OUTD
#define HID 256
#define MOUT 128
#define NBLK 49     // ceil(NN/1024)

// ---- scratch (device globals: allocation-free) ----
__device__ __half g_h[(size_t)NN * HD];       // transformed features (fp16)
__device__ __half g_act[(size_t)NN * HD];     // relu(num/den): GEMM2 input (fp16)
__device__ __half g_hidden[(size_t)NN * HID]; // MLP hidden (fp16)
__device__ float g_s_src[NN * HEADS];
__device__ float g_s_dst[NN * HEADS];
// weights: fp16, pre-transposed to [N][K] (col-major B for m16n8k16)
__device__ __half g_WcT[HD * IND];
__device__ __half g_W1T[HID * HD];
__device__ __half g_W2T[MOUT * HID];
// CSR-by-dst build
__device__ int g_cnt[NN];
__device__ int g_off[NN + 1];
__device__ int g_pos[NN];
__device__ int g_esrc[NE];
__device__ int g_bsum[NBLK];
__device__ int g_boff[NBLK];

// ---- pack weights (fp16, transposed) + zero g_cnt ----
__global__ void pack_w_kernel(const float* __restrict__ Wn,
                              const float* __restrict__ W1,
                              const float* __restrict__ W2) {
    int i = blockIdx.x * blockDim.x + threadIdx.x;
    if (i < HD * IND) {          // WcT[j][c] = Wn[h, c, d], j = h*64+d
        int j = i / IND;
        int c = i % IND;
        int h = j >> 6;
        int d = j & 63;
        g_WcT[i] = __float2half_rn(Wn[h * (IND * OUTD) + c * OUTD + d]);
    }
    if (i < HID * HD) {          // W1T[n][k] = W1[k][n]
        int n = i / HD;
        int k = i % HD;
        g_W1T[i] = __float2half_rn(W1[k * HID + n]);
    }
    if (i < MOUT * HID) {        // W2T[n][k] = W2[k][n]
        int n = i / HID;
        int k = i % HID;
        g_W2T[i] = __float2half_rn(W2[k * MOUT + n]);
    }
    if (i < NN) g_cnt[i] = 0;
}

// ---- histogram of dst ----
__global__ void hist_kernel(const int* __restrict__ dst) {
    int i = blockIdx.x * blockDim.x + threadIdx.x;
    if (i < NE) atomicAdd(&g_cnt[dst[i]], 1);
}

// ---- 3-phase scan ----
__global__ void scan_blocks_kernel() {
    __shared__ int wsum[32];
    int tid = threadIdx.x;
    int i = blockIdx.x * 1024 + tid;
    int v = (i < NN) ? g_cnt[i] : 0;
#pragma unroll
    for (int o = 16; o > 0; o >>= 1) v += __shfl_down_sync(0xffffffffu, v, o);
    if ((tid & 31) == 0) wsum[tid >> 5] = v;
    __syncthreads();
    if (tid < 32) {
        int s = wsum[tid];
#pragma unroll
        for (int o = 16; o > 0; o >>= 1) s += __shfl_down_sync(0xffffffffu, s, o);
        if (tid == 0) g_bsum[blockIdx.x] = s;
    }
}

__global__ void scan_top_kernel() {
    __shared__ int s[64];
    int t = threadIdx.x;
    int v = (t < NBLK) ? g_bsum[t] : 0;
    s[t] = v;
    __syncthreads();
#pragma unroll
    for (int o = 1; o < 64; o <<= 1) {
        int x = (t >= o) ? s[t - o] : 0;
        __syncthreads();
        s[t] += x;
        __syncthreads();
    }
    if (t < NBLK) g_boff[t] = s[t] - v;
    if (t == 0) g_off[NN] = NE;
}

__global__ void scan_final_kernel() {
    __shared__ int wsum[32];
    int tid = threadIdx.x;
    int lane = tid & 31;
    int wid = tid >> 5;
    int i = blockIdx.x * 1024 + tid;
    int v = (i < NN) ? g_cnt[i] : 0;
    int x = v;
#pragma unroll
    for (int o = 1; o < 32; o <<= 1) {
        int t = __shfl_up_sync(0xffffffffu, x, o);
        if (lane >= o) x += t;
    }
    if (lane == 31) wsum[wid] = x;
    __syncthreads();
    if (wid == 0) {
        int s = wsum[lane];
#pragma unroll
        for (int o = 1; o < 32; o <<= 1) {
            int t = __shfl_up_sync(0xffffffffu, s, o);
            if (lane >= o) s += t;
        }
        wsum[lane] = s;
    }
    __syncthreads();
    int excl = x - v + ((wid > 0) ? wsum[wid - 1] : 0) + g_boff[blockIdx.x];
    if (i < NN) { g_off[i] = excl; g_pos[i] = excl; }
}

// ---- scatter edges into dst-grouped order ----
__global__ void scatter_kernel(const int* __restrict__ src, const int* __restrict__ dst) {
    int i = blockIdx.x * blockDim.x + threadIdx.x;
    if (i < NE) {
        int d = dst[i];
        int p = atomicAdd(&g_pos[d], 1);
        g_esrc[p] = src[i];
    }
}

__device__ __forceinline__ void mma_f16(float& c0, float& c1, float& c2, float& c3,
                                        unsigned a0, unsigned a1, unsigned a2, unsigned a3,
                                        unsigned b0, unsigned b1) {
    asm volatile("mma.sync.aligned.m16n8k16.row.col.f32.f16.f16.f32 "
                 "{%0,%1,%2,%3}, {%4,%5,%6,%7}, {%8,%9}, {%0,%1,%2,%3};"
                 : "+f"(c0), "+f"(c1), "+f"(c2), "+f"(c3)
                 : "r"(a0), "r"(a1), "r"(a2), "r"(a3), "r"(b0), "r"(b1));
}

// ---- fp16 tensor-core GEMM, single-buffer + reg prefetch + LDSM frag loads ----
// C[M,N] = act(A @ BT^T + bias). BT is fp16 [N][K] (pre-transposed).
// EPI 0: none. 1: +bias, relu. 2: +bias.
// SCORE 1: emit g_s_src/g_s_dst from fp32 accumulators (GEMM1 only).
// AHALF: A is fp16 (else fp32). CHALF: C is fp16 (else fp32).
template<int EPI, int SCORE, int AHALF, int CHALF>
__global__ void __launch_bounds__(256, 2)
gemm_f16_kernel(const void* __restrict__ Av, const __half* __restrict__ BT,
                const float* __restrict__ bias,
                const float* __restrict__ asrc, const float* __restrict__ adst,
                void* __restrict__ Cv, int M, int N, int K)
{
    const int BM = 128, BN = 128, BK = 32;
    const int PAD = 40;                 // 80B row stride: conflict-free for LDSM phases
    __shared__ __half As[BM * PAD];     // [m][k]
    __shared__ __half Bs[BN * PAD];     // [n][k]

    const float*  Af = (const float*)Av;
    const __half* Ah = (const __half*)Av;
    float*  Cf = (float*)Cv;
    __half* Ch = (__half*)Cv;

    int tid = threadIdx.x;
    int wid = tid >> 5;
    int lane = tid & 31;
    int grp = lane >> 2;
    int tig = lane & 3;

    int warp_m = (wid & 3) * 32;
    int warp_n = (wid >> 2) * 64;

    int m0 = blockIdx.x * BM;
    int n0 = blockIdx.y * BN;

    float4 ra[4];
    uint4 rah[2];
    uint4 rb[2];

    // prologue loads (k0 = 0)
    if (AHALF) {
#pragma unroll
        for (int j = 0; j < 2; j++) {
            int i = tid + j * 256;
            int row = i >> 2;
            int c8 = (i & 3) * 8;
            int gm = m0 + row;
            rah[j] = make_uint4(0u, 0u, 0u, 0u);
            if (gm < M) rah[j] = *(const uint4*)(Ah + (size_t)gm * K + c8);
        }
    } else {
#pragma unroll
        for (int j = 0; j < 4; j++) {
            int i = tid + j * 256;
            int row = i >> 3;
            int c4 = (i & 7) * 4;
            int gm = m0 + row;
            ra[j] = make_float4(0.f, 0.f, 0.f, 0.f);
            if (gm < M) ra[j] = *(const float4*)(Af + (size_t)gm * K + c4);
        }
    }
#pragma unroll
    for (int j = 0; j < 2; j++) {
        int i = tid + j * 256;
        int n = i >> 2;
        int c8 = (i & 3) * 8;
        rb[j] = *(const uint4*)(BT + (size_t)(n0 + n) * K + c8);
    }

    float acc[2][8][4];
#pragma unroll
    for (int i = 0; i < 2; i++)
#pragma unroll
        for (int j = 0; j < 8; j++)
#pragma unroll
            for (int q = 0; q < 4; q++) acc[i][j][q] = 0.0f;

    for (int k0 = 0; k0 < K; k0 += BK) {
        // store current tile to smem
        if (AHALF) {
#pragma unroll
            for (int j = 0; j < 2; j++) {
                int i = tid + j * 256;
                int row = i >> 2;
                int c8 = (i & 3) * 8;
                *(uint4*)&As[row * PAD + c8] = rah[j];
            }
        } else {
#pragma unroll
            for (int j = 0; j < 4; j++) {
                int i = tid + j * 256;
                int row = i >> 3;
                int c4 = (i & 7) * 4;
                __half2* p = (__half2*)&As[row * PAD + c4];
                p[0] = __floats2half2_rn(ra[j].x, ra[j].y);
                p[1] = __floats2half2_rn(ra[j].z, ra[j].w);
            }
        }
#pragma unroll
        for (int j = 0; j < 2; j++) {
            int i = tid + j * 256;
            int n = i >> 2;
            int c8 = (i & 3) * 8;
            *(uint4*)&Bs[n * PAD + c8] = rb[j];
        }
        __syncthreads();

        // prefetch next tile while computing
        int kn = k0 + BK;
        if (kn < K) {
            if (AHALF) {
#pragma unroll
                for (int j = 0; j < 2; j++) {
                    int i = tid + j * 256;
                    int row = i >> 2;
                    int c8 = (i & 3) * 8;
                    int gm = m0 + row;
                    rah[j] = make_uint4(0u, 0u, 0u, 0u);
                    if (gm < M) rah[j] = *(const uint4*)(Ah + (size_t)gm * K + kn + c8);
                }
            } else {
#pragma unroll
                for (int j = 0; j < 4; j++) {
                    int i = tid + j * 256;
                    int row = i >> 3;
                    int c4 = (i & 7) * 4;
                    int gm = m0 + row;
                    ra[j] = make_float4(0.f, 0.f, 0.f, 0.f);
                    if (gm < M) ra[j] = *(const float4*)(Af + (size_t)gm * K + kn + c4);
                }
            }
#pragma unroll
            for (int j = 0; j < 2; j++) {
                int i = tid + j * 256;
                int n = i >> 2;
                int c8 = (i & 3) * 8;
                rb[j] = *(const uint4*)(BT + (size_t)(n0 + n) * K + kn + c8);
            }
        }

        // compute: 2 k-steps of m16n8k16, fragments via ldmatrix.x4
#pragma unroll
        for (int kk = 0; kk < BK; kk += 16) {
            unsigned af[2][4];
#pragma unroll
            for (int mt = 0; mt < 2; mt++) {
                int r = warp_m + mt * 16 + (lane & 15);
                int c = kk + (lane >> 4) * 8;
                unsigned addr = (unsigned)__cvta_generic_to_shared(&As[r * PAD + c]);
                asm volatile("ldmatrix.sync.aligned.m8n8.x4.shared.b16 {%0,%1,%2,%3}, [%4];"
                             : "=r"(af[mt][0]), "=r"(af[mt][1]),
                               "=r"(af[mt][2]), "=r"(af[mt][3])
                             : "r"(addr));
            }
            unsigned bf[8][2];
#pragma unroll
            for (int nt2 = 0; nt2 < 4; nt2++) {
                int nr = warp_n + nt2 * 16 + (lane & 7) + ((lane >> 4) << 3);
                int c = kk + ((lane >> 3) & 1) * 8;
                unsigned addr = (unsigned)__cvta_generic_to_shared(&Bs[nr * PAD + c]);
                unsigned t0, t1, t2, t3;
                asm volatile("ldmatrix.sync.aligned.m8n8.x4.shared.b16 {%0,%1,%2,%3}, [%4];"
                             : "=r"(t0), "=r"(t1), "=r"(t2), "=r"(t3)
                             : "r"(addr));
                bf[nt2 * 2][0] = t0; bf[nt2 * 2][1] = t1;
                bf[nt2 * 2 + 1][0] = t2; bf[nt2 * 2 + 1][1] = t3;
            }
#pragma unroll
            for (int nt = 0; nt < 8; nt++)
#pragma unroll
                for (int mt = 0; mt < 2; mt++)
                    mma_f16(acc[mt][nt][0], acc[mt][nt][1], acc[mt][nt][2], acc[mt][nt][3],
                            af[mt][0], af[mt][1], af[mt][2], af[mt][3],
                            bf[nt][0], bf[nt][1]);
        }
        __syncthreads();
    }

    // --- epilogue ---
    int head = (n0 + warp_n) >> 6;   // warp tile spans exactly one head
#pragma unroll
    for (int mt = 0; mt < 2; mt++) {
#pragma unroll
        for (int half = 0; half < 2; half++) {
            int gm = m0 + warp_m + mt * 16 + grp + half * 8;
            if (gm >= M) continue;
            float ss = 0.0f, sd = 0.0f;
#pragma unroll
            for (int nt = 0; nt < 8; nt++) {
                int gn = n0 + warp_n + nt * 8 + tig * 2;
                float v0 = acc[mt][nt][half * 2 + 0];
                float v1 = acc[mt][nt][half * 2 + 1];
                if (EPI >= 1) { v0 += bias[gn]; v1 += bias[gn + 1]; }
                if (EPI == 1) { v0 = fmaxf(v0, 0.0f); v1 = fmaxf(v1, 0.0f); }
                if (SCORE) {
                    float2 a2 = *(const float2*)(asrc + gn);
                    float2 d2 = *(const float2*)(adst + gn);
                    ss += v0 * a2.x + v1 * a2.y;
                    sd += v0 * d2.x + v1 * d2.y;
                }
                if (CHALF) {
                    *(__half2*)(Ch + (size_t)gm * N + gn) = __floats2half2_rn(v0, v1);
                } else {
                    *(float2*)(Cf + (size_t)gm * N + gn) = make_float2(v0, v1);
                }
            }
            if (SCORE) {
                ss += __shfl_down_sync(0xffffffffu, ss, 2);
                ss += __shfl_down_sync(0xffffffffu, ss, 1);
                sd += __shfl_down_sync(0xffffffffu, sd, 2);
                sd += __shfl_down_sync(0xffffffffu, sd, 1);
                if (tig == 0) {
                    g_s_src[gm * HEADS + head] = ss;
                    g_s_dst[gm * HEADS + head] = sd;
                }
            }
        }
    }
}

// ---- gather kernel: one warp per dst node, CSR edges, fp16 h, fp32 accum ----
__global__ void gather_kernel() {
    int gw = (blockIdx.x * blockDim.x + threadIdx.x) >> 5;
    int lane = threadIdx.x & 31;
    if (gw >= NN) return;

    int beg = g_off[gw];
    int end = g_off[gw + 1];
    int head = lane >> 3;           // lane covers halves [lane*8, lane*8+8)

    float sdst = (lane < HEADS) ? g_s_dst[gw * HEADS + lane] : 0.0f;

    float acc[8];
#pragma unroll
    for (int q = 0; q < 8; q++) acc[q] = 0.0f;
    float den = 0.0f;

    for (int chunk = beg; chunk < end; chunk += 32) {
        int myE = (chunk + lane < end) ? g_esrc[chunk + lane] : 0;
        int cnt = min(32, end - chunk);
        for (int j = 0; j < cnt; j++) {
            int s = __shfl_sync(0xffffffffu, myE, j);
            float ex = 0.0f;
            if (lane < HEADS) {
                float e = g_s_src[s * HEADS + lane] + sdst;
                e = e > 0.0f ? e : 0.2f * e;
                ex = __expf(e);
                den += ex;
            }
            float exh = __shfl_sync(0xffffffffu, ex, head);
            uint4 v = ((const uint4*)(g_h + (size_t)s * HD))[lane];
            const __half2* hv = (const __half2*)&v;
#pragma unroll
            for (int q = 0; q < 4; q++) {
                float2 f = __half22float2(hv[q]);
                acc[q * 2]     = fmaf(exh, f.x, acc[q * 2]);
                acc[q * 2 + 1] = fmaf(exh, f.y, acc[q * 2 + 1]);
            }
        }
    }

    float denh = __shfl_sync(0xffffffffu, den, head);
    float inv = denh > 0.0f ? 1.0f / denh : 0.0f;

    uint4 outv;
    __half2* ov = (__half2*)&outv;
#pragma unroll
    for (int q = 0; q < 4; q++) {
        float x = fmaxf(acc[q * 2]     * inv, 0.0f);
        float y = fmaxf(acc[q * 2 + 1] * inv, 0.0f);
        ov[q] = __floats2half2_rn(x, y);
    }
    ((uint4*)(g_act + (size_t)gw * HD))[lane] = outv;
}

extern "C" void kernel_launch(void* const* d_in, const int* in_sizes, int n_in,
                              void* d_out, int out_size) {
    const float* node_emb = (const float*)d_in[0];
    const int*   src      = (const int*)d_in[1];
    const int*   dst      = (const int*)d_in[2];
    const float* W_n      = (const float*)d_in[3];
    const float* a_src    = (const float*)d_in[4];
    const float* a_dst    = (const float*)d_in[5];
    const float* W1       = (const float*)d_in[6];
    const float* b1       = (const float*)d_in[7];
    const float* W2       = (const float*)d_in[8];
    const float* b2       = (const float*)d_in[9];
    float* out = (float*)d_out;

    __half* h_ptr;   cudaGetSymbolAddress((void**)&h_ptr, g_h);
    __half* act_ptr; cudaGetSymbolAddress((void**)&act_ptr, g_act);
    __half* hid_ptr; cudaGetSymbolAddress((void**)&hid_ptr, g_hidden);
    __half* wcT_ptr; cudaGetSymbolAddress((void**)&wcT_ptr, g_WcT);
    __half* w1T_ptr; cudaGetSymbolAddress((void**)&w1T_ptr, g_W1T);
    __half* w2T_ptr; cudaGetSymbolAddress((void**)&w2T_ptr, g_W2T);

    // 1. pack weights (fp16 transposed) + zero counts
    pack_w_kernel<<<(HID * HD + 255) / 256, 256>>>(W_n, W1, W2);

    // 2. CSR-by-dst build (3-phase scan)
    hist_kernel<<<(NE + 255) / 256, 256>>>(dst);
    scan_blocks_kernel<<<NBLK, 1024>>>();
    scan_top_kernel<<<1, 64>>>();
    scan_final_kernel<<<NBLK, 1024>>>();
    scatter_kernel<<<(NE + 255) / 256, 256>>>(src, dst);

    // 3. GEMM1 + fused scores: h(fp16) = X @ Wc ; s_src/s_dst(fp32)
    {
        dim3 grid((NN + 127) / 128, HD / 128);
        gemm_f16_kernel<0, 1, 0, 1><<<grid, 256>>>(node_emb, wcT_ptr, nullptr,
                                                   a_src, a_dst, h_ptr, NN, HD, IND);
    }

    // 4. gather: per-dst softmax aggregation -> g_act (fp16, normalized + relu)
    gather_kernel<<<(NN * 32 + 255) / 256, 256>>>();

    // 5. GEMM2: hidden(fp16) = relu( act(fp16) @ W1 + b1 )
    {
        dim3 grid((NN + 127) / 128, HID / 128);
        gemm_f16_kernel<1, 0, 1, 1><<<grid, 256>>>(act_ptr, w1T_ptr, b1,
                                                   nullptr, nullptr, hid_ptr, NN, HID, HD);
    }

    // 6. GEMM3: out(fp32) = hidden(fp16) @ W2 + b2
    {
        dim3 grid((NN + 127) / 128, MOUT / 128);
        gemm_f16_kernel<2, 0, 1, 0><<<grid, 256>>>(hid_ptr, w2T_ptr, b2,
                                                   nullptr, nullptr, out, NN, MOUT, HID);
    }
}

// round 15
// speedup vs baseline: 1.1847x; 1.0002x over previous
#include <cuda_runtime.h>
#include <cuda_fp16.h>
#include <cuda_bf16.h>

#define NN 50000
#define NE 800000
#define IND 128
#define OUTD 64
#define HEADS 4
#define HD 256      // HEADS*OUTD
#define HID 256
#define MOUT 128
#define NBLK 49     // ceil(NN/1024)

// ---- scratch (device globals: allocation-free) ----
__device__ __half g_xh[(size_t)NN * IND];     // node_embeddings in fp16
__device__ __half g_h[(size_t)NN * HD];       // transformed features (fp16)
__device__ __half g_act[(size_t)NN * HD];     // relu(num/den): GEMM2 input (fp16)
__device__ __half g_hidden[(size_t)NN * HID]; // MLP hidden (fp16)
__device__ float g_s_src[NN * HEADS];
__device__ float g_s_dst[NN * HEADS];
// weights: fp16, pre-transposed to [N][K] (col-major B for m16n8k16)
__device__ __half g_WcT[HD * IND];
__device__ __half g_W1T[HID * HD];
__device__ __half g_W2T[MOUT * HID];
// CSR-by-dst build
__device__ int g_cnt[NN];
__device__ int g_off[NN + 1];
__device__ int g_pos[NN];
__device__ int g_esrc[NE];
__device__ int g_bsum[NBLK];

// ---- pack weights (fp16, transposed) + zero g_cnt ----
__global__ void pack_w_kernel(const float* __restrict__ Wn,
                              const float* __restrict__ W1,
                              const float* __restrict__ W2) {
    int i = blockIdx.x * blockDim.x + threadIdx.x;
    if (i < HD * IND) {          // WcT[j][c] = Wn[h, c, d], j = h*64+d
        int j = i / IND;
        int c = i % IND;
        int h = j >> 6;
        int d = j & 63;
        g_WcT[i] = __float2half_rn(Wn[h * (IND * OUTD) + c * OUTD + d]);
    }
    if (i < HID * HD) {          // W1T[n][k] = W1[k][n]
        int n = i / HD;
        int k = i % HD;
        g_W1T[i] = __float2half_rn(W1[k * HID + n]);
    }
    if (i < MOUT * HID) {        // W2T[n][k] = W2[k][n]
        int n = i / HID;
        int k = i % HID;
        g_W2T[i] = __float2half_rn(W2[k * MOUT + n]);
    }
    if (i < NN) g_cnt[i] = 0;
}

// ---- convert node embeddings fp32 -> fp16 (4 per thread) ----
__global__ void convert_x_kernel(const float* __restrict__ x) {
    int i = blockIdx.x * blockDim.x + threadIdx.x;
    if (i < NN * IND / 4) {
        float4 v = ((const float4*)x)[i];
        uint2 o;
        ((__half2*)&o)[0] = __floats2half2_rn(v.x, v.y);
        ((__half2*)&o)[1] = __floats2half2_rn(v.z, v.w);
        ((uint2*)g_xh)[i] = o;
    }
}

// ---- histogram of dst ----
__global__ void hist_kernel(const int* __restrict__ dst) {
    int i = blockIdx.x * blockDim.x + threadIdx.x;
    if (i < NE) atomicAdd(&g_cnt[dst[i]], 1);
}

// ---- 2-phase scan: block sums, then per-block scan with inline top-scan ----
__global__ void scan_blocks_kernel() {
    __shared__ int wsum[32];
    int tid = threadIdx.x;
    int i = blockIdx.x * 1024 + tid;
    int v = (i < NN) ? g_cnt[i] : 0;
#pragma unroll
    for (int o = 16; o > 0; o >>= 1) v += __shfl_down_sync(0xffffffffu, v, o);
    if ((tid & 31) == 0) wsum[tid >> 5] = v;
    __syncthreads();
    if (tid < 32) {
        int s = wsum[tid];
#pragma unroll
        for (int o = 16; o > 0; o >>= 1) s += __shfl_down_sync(0xffffffffu, s, o);
        if (tid == 0) g_bsum[blockIdx.x] = s;
    }
}

__global__ void scan_final_kernel() {
    __shared__ int wsum[32];
    __shared__ int sb[64];            // inclusive prefix of block sums
    int tid = threadIdx.x;
    int lane = tid & 31;
    int wid = tid >> 5;

    // warp 0: inline scan of the 49 block sums (redundant per block, trivial cost)
    if (wid == 0) {
        int v0 = (lane < NBLK) ? g_bsum[lane] : 0;
        int v1 = (lane + 32 < NBLK) ? g_bsum[lane + 32] : 0;
#pragma unroll
        for (int o = 1; o < 32; o <<= 1) {
            int t = __shfl_up_sync(0xffffffffu, v0, o);
            if (lane >= o) v0 += t;
        }
        int tot0 = __shfl_sync(0xffffffffu, v0, 31);
#pragma unroll
        for (int o = 1; o < 32; o <<= 1) {
            int t = __shfl_up_sync(0xffffffffu, v1, o);
            if (lane >= o) v1 += t;
        }
        sb[lane] = v0;
        sb[lane + 32] = v1 + tot0;
    }
    __syncthreads();
    int boff = (blockIdx.x > 0) ? sb[blockIdx.x - 1] : 0;

    int i = blockIdx.x * 1024 + tid;
    int v = (i < NN) ? g_cnt[i] : 0;
    int x = v;
#pragma unroll
    for (int o = 1; o < 32; o <<= 1) {
        int t = __shfl_up_sync(0xffffffffu, x, o);
        if (lane >= o) x += t;
    }
    if (lane == 31) wsum[wid] = x;
    __syncthreads();
    if (wid == 0) {
        int s = wsum[lane];
#pragma unroll
        for (int o = 1; o < 32; o <<= 1) {
            int t = __shfl_up_sync(0xffffffffu, s, o);
            if (lane >= o) s += t;
        }
        wsum[lane] = s;
    }
    __syncthreads();
    int excl = x - v + ((wid > 0) ? wsum[wid - 1] : 0) + boff;
    if (i < NN) { g_off[i] = excl; g_pos[i] = excl; }
    if (blockIdx.x == 0 && tid == 0) g_off[NN] = NE;
}

// ---- scatter edges into dst-grouped order ----
__global__ void scatter_kernel(const int* __restrict__ src, const int* __restrict__ dst) {
    int i = blockIdx.x * blockDim.x + threadIdx.x;
    if (i < NE) {
        int d = dst[i];
        int p = atomicAdd(&g_pos[d], 1);
        g_esrc[p] = src[i];
    }
}

__device__ __forceinline__ void mma_f16(float& c0, float& c1, float& c2, float& c3,
                                        unsigned a0, unsigned a1, unsigned a2, unsigned a3,
                                        unsigned b0, unsigned b1) {
    asm volatile("mma.sync.aligned.m16n8k16.row.col.f32.f16.f16.f32 "
                 "{%0,%1,%2,%3}, {%4,%5,%6,%7}, {%8,%9}, {%0,%1,%2,%3};"
                 : "+f"(c0), "+f"(c1), "+f"(c2), "+f"(c3)
                 : "r"(a0), "r"(a1), "r"(a2), "r"(a3), "r"(b0), "r"(b1));
}

__device__ __forceinline__ void cp_async16(void* smem_dst, const void* gmem_src, bool valid) {
    unsigned saddr = (unsigned)__cvta_generic_to_shared(smem_dst);
    int sz = valid ? 16 : 0;
    asm volatile("cp.async.cg.shared.global [%0], [%1], 16, %2;"
                 :: "r"(saddr), "l"(gmem_src), "r"(sz));
}

// ---- fp16 tensor-core GEMM: cp.async 2-stage pipeline + LDSM frag loads ----
// C[M,N] = act(A @ BT^T + bias). A fp16 [M][K], BT fp16 [N][K].
// EPI 0: none. 1: +bias, relu. 2: +bias.
// SCORE 1: emit g_s_src/g_s_dst from fp32 accumulators (GEMM1 only).
// CHALF: C is fp16 (else fp32).
template<int EPI, int SCORE, int CHALF>
__global__ void __launch_bounds__(256, 2)
gemm_f16_kernel(const __half* __restrict__ A, const __half* __restrict__ BT,
                const float* __restrict__ bias,
                const float* __restrict__ asrc, const float* __restrict__ adst,
                void* __restrict__ Cv, int M, int N, int K)
{
    const int BM = 128, BN = 128, BK = 32;
    const int PAD = 40;                    // 80B row stride: conflict-free LDSM phases
    __shared__ __half As[2][BM * PAD];     // [m][k]
    __shared__ __half Bs[2][BN * PAD];     // [n][k]

    float*  Cf = (float*)Cv;
    __half* Ch = (__half*)Cv;

    int tid = threadIdx.x;
    int wid = tid >> 5;
    int lane = tid & 31;
    int grp = lane >> 2;
    int tig = lane & 3;

    int warp_m = (wid & 3) * 32;
    int warp_n = (wid >> 2) * 64;

    int m0 = blockIdx.x * BM;
    int n0 = blockIdx.y * BN;

    // per-thread copy coords: i = tid + j*256; row = i>>2; c8 = (i&3)*8  (2 chunks each)
    auto copy_tile = [&](int buf, int k0) {
#pragma unroll
        for (int j = 0; j < 2; j++) {
            int i = tid + j * 256;
            int row = i >> 2;
            int c8 = (i & 3) * 8;
            int gm = m0 + row;
            bool ok = gm < M;
            int gma = ok ? gm : (M - 1);
            cp_async16(&As[buf][row * PAD + c8], A + (size_t)gma * K + k0 + c8, ok);
        }
#pragma unroll
        for (int j = 0; j < 2; j++) {
            int i = tid + j * 256;
            int n = i >> 2;
            int c8 = (i & 3) * 8;
            cp_async16(&Bs[buf][n * PAD + c8], BT + (size_t)(n0 + n) * K + k0 + c8, true);
        }
        asm volatile("cp.async.commit_group;");
    };

    float acc[2][8][4];
#pragma unroll
    for (int i = 0; i < 2; i++)
#pragma unroll
        for (int j = 0; j < 8; j++)
#pragma unroll
            for (int q = 0; q < 4; q++) acc[i][j][q] = 0.0f;

    copy_tile(0, 0);   // prologue

    int buf = 0;
    for (int k0 = 0; k0 < K; k0 += BK) {
        asm volatile("cp.async.wait_group 0;");
        __syncthreads();                      // stage buf ready for all warps

        int kn = k0 + BK;
        if (kn < K) copy_tile(buf ^ 1, kn);   // overlaps with MMAs below

        // compute: 2 k-steps of m16n8k16, fragments via ldmatrix.x4
#pragma unroll
        for (int kk = 0; kk < BK; kk += 16) {
            unsigned af[2][4];
#pragma unroll
            for (int mt = 0; mt < 2; mt++) {
                int r = warp_m + mt * 16 + (lane & 15);
                int c = kk + (lane >> 4) * 8;
                unsigned addr = (unsigned)__cvta_generic_to_shared(&As[buf][r * PAD + c]);
                asm volatile("ldmatrix.sync.aligned.m8n8.x4.shared.b16 {%0,%1,%2,%3}, [%4];"
                             : "=r"(af[mt][0]), "=r"(af[mt][1]),
                               "=r"(af[mt][2]), "=r"(af[mt][3])
                             : "r"(addr));
            }
            unsigned bf[8][2];
#pragma unroll
            for (int nt2 = 0; nt2 < 4; nt2++) {
                int nr = warp_n + nt2 * 16 + (lane & 7) + ((lane >> 4) << 3);
                int c = kk + ((lane >> 3) & 1) * 8;
                unsigned addr = (unsigned)__cvta_generic_to_shared(&Bs[buf][nr * PAD + c]);
                unsigned t0, t1, t2, t3;
                asm volatile("ldmatrix.sync.aligned.m8n8.x4.shared.b16 {%0,%1,%2,%3}, [%4];"
                             : "=r"(t0), "=r"(t1), "=r"(t2), "=r"(t3)
                             : "r"(addr));
                bf[nt2 * 2][0] = t0; bf[nt2 * 2][1] = t1;
                bf[nt2 * 2 + 1][0] = t2; bf[nt2 * 2 + 1][1] = t3;
            }
#pragma unroll
            for (int nt = 0; nt < 8; nt++)
#pragma unroll
                for (int mt = 0; mt < 2; mt++)
                    mma_f16(acc[mt][nt][0], acc[mt][nt][1], acc[mt][nt][2], acc[mt][nt][3],
                            af[mt][0], af[mt][1], af[mt][2], af[mt][3],
                            bf[nt][0], bf[nt][1]);
        }
        __syncthreads();                      // all warps done reading buf
        buf ^= 1;
    }

    // --- epilogue ---
    int head = (n0 + warp_n) >> 6;   // warp tile spans exactly one head
#pragma unroll
    for (int mt = 0; mt < 2; mt++) {
#pragma unroll
        for (int half = 0; half < 2; half++) {
            int gm = m0 + warp_m + mt * 16 + grp + half * 8;
            if (gm >= M) continue;
            float ss = 0.0f, sd = 0.0f;
#pragma unroll
            for (int nt = 0; nt < 8; nt++) {
                int gn = n0 + warp_n + nt * 8 + tig * 2;
                float v0 = acc[mt][nt][half * 2 + 0];
                float v1 = acc[mt][nt][half * 2 + 1];
                if (EPI >= 1) { v0 += bias[gn]; v1 += bias[gn + 1]; }
                if (EPI == 1) { v0 = fmaxf(v0, 0.0f); v1 = fmaxf(v1, 0.0f); }
                if (SCORE) {
                    float2 a2 = *(const float2*)(asrc + gn);
                    float2 d2 = *(const float2*)(adst + gn);
                    ss += v0 * a2.x + v1 * a2.y;
                    sd += v0 * d2.x + v1 * d2.y;
                }
                if (CHALF) {
                    *(__half2*)(Ch + (size_t)gm * N + gn) = __floats2half2_rn(v0, v1);
                } else {
                    *(float2*)(Cf + (size_t)gm * N + gn) = make_float2(v0, v1);
                }
            }
            if (SCORE) {
                ss += __shfl_down_sync(0xffffffffu, ss, 2);
                ss += __shfl_down_sync(0xffffffffu, ss, 1);
                sd += __shfl_down_sync(0xffffffffu, sd, 2);
                sd += __shfl_down_sync(0xffffffffu, sd, 1);
                if (tig == 0) {
                    g_s_src[gm * HEADS + head] = ss;
                    g_s_dst[gm * HEADS + head] = sd;
                }
            }
        }
    }
}

// ---- gather kernel: one warp per dst node, CSR edges, fp16 h, fp32 accum ----
__global__ void gather_kernel() {
    int gw = (blockIdx.x * blockDim.x + threadIdx.x) >> 5;
    int lane = threadIdx.x & 31;
    if (gw >= NN) return;

    int beg = g_off[gw];
    int end = g_off[gw + 1];
    int head = lane >> 3;           // lane covers halves [lane*8, lane*8+8)

    float sdst = (lane < HEADS) ? g_s_dst[gw * HEADS + lane] : 0.0f;

    float acc[8];
#pragma unroll
    for (int q = 0; q < 8; q++) acc[q] = 0.0f;
    float den = 0.0f;

    for (int chunk = beg; chunk < end; chunk += 32) {
        int myE = (chunk + lane < end) ? g_esrc[chunk + lane] : 0;
        int cnt = min(32, end - chunk);
        for (int j = 0; j < cnt; j++) {
            int s = __shfl_sync(0xffffffffu, myE, j);
            float ex = 0.0f;
            if (lane < HEADS) {
                float e = g_s_src[s * HEADS + lane] + sdst;
                e = e > 0.0f ? e : 0.2f * e;
                ex = __expf(e);
                den += ex;
            }
            float exh = __shfl_sync(0xffffffffu, ex, head);
            uint4 v = ((const uint4*)(g_h + (size_t)s * HD))[lane];
            const __half2* hv = (const __half2*)&v;
#pragma unroll
            for (int q = 0; q < 4; q++) {
                float2 f = __half22float2(hv[q]);
                acc[q * 2]     = fmaf(exh, f.x, acc[q * 2]);
                acc[q * 2 + 1] = fmaf(exh, f.y, acc[q * 2 + 1]);
            }
        }
    }

    float denh = __shfl_sync(0xffffffffu, den, head);
    float inv = denh > 0.0f ? 1.0f / denh : 0.0f;

    uint4 outv;
    __half2* ov = (__half2*)&outv;
#pragma unroll
    for (int q = 0; q < 4; q++) {
        float x = fmaxf(acc[q * 2]     * inv, 0.0f);
        float y = fmaxf(acc[q * 2 + 1] * inv, 0.0f);
        ov[q] = __floats2half2_rn(x, y);
    }
    ((uint4*)(g_act + (size_t)gw * HD))[lane] = outv;
}

extern "C" void kernel_launch(void* const* d_in, const int* in_sizes, int n_in,
                              void* d_out, int out_size) {
    const float* node_emb = (const float*)d_in[0];
    const int*   src      = (const int*)d_in[1];
    const int*   dst      = (const int*)d_in[2];
    const float* W_n      = (const float*)d_in[3];
    const float* a_src    = (const float*)d_in[4];
    const float* a_dst    = (const float*)d_in[5];
    const float* W1       = (const float*)d_in[6];
    const float* b1       = (const float*)d_in[7];
    const float* W2       = (const float*)d_in[8];
    const float* b2       = (const float*)d_in[9];
    float* out = (float*)d_out;

    __half* xh_ptr;  cudaGetSymbolAddress((void**)&xh_ptr, g_xh);
    __half* h_ptr;   cudaGetSymbolAddress((void**)&h_ptr, g_h);
    __half* act_ptr; cudaGetSymbolAddress((void**)&act_ptr, g_act);
    __half* hid_ptr; cudaGetSymbolAddress((void**)&hid_ptr, g_hidden);
    __half* wcT_ptr; cudaGetSymbolAddress((void**)&wcT_ptr, g_WcT);
    __half* w1T_ptr; cudaGetSymbolAddress((void**)&w1T_ptr, g_W1T);
    __half* w2T_ptr; cudaGetSymbolAddress((void**)&w2T_ptr, g_W2T);

    // 1. pack weights (fp16 transposed) + zero counts; convert X to fp16
    pack_w_kernel<<<(HID * HD + 255) / 256, 256>>>(W_n, W1, W2);
    convert_x_kernel<<<(NN * IND / 4 + 255) / 256, 256>>>(node_emb);

    // 2. CSR-by-dst build
    hist_kernel<<<(NE + 255) / 256, 256>>>(dst);
    scan_blocks_kernel<<<NBLK, 1024>>>();
    scan_final_kernel<<<NBLK, 1024>>>();
    scatter_kernel<<<(NE + 255) / 256, 256>>>(src, dst);

    // 3. GEMM1 + fused scores: h(fp16) = X @ Wc ; s_src/s_dst(fp32)
    {
        dim3 grid((NN + 127) / 128, HD / 128);
        gemm_f16_kernel<0, 1, 1><<<grid, 256>>>(xh_ptr, wcT_ptr, nullptr,
                                                a_src, a_dst, h_ptr, NN, HD, IND);
    }

    // 4. gather: per-dst softmax aggregation -> g_act (fp16, normalized + relu)
    gather_kernel<<<(NN * 32 + 255) / 256, 256>>>();

    // 5. GEMM2: hidden(fp16) = relu( act(fp16) @ W1 + b1 )
    {
        dim3 grid((NN + 127) / 128, HID / 128);
        gemm_f16_kernel<1, 0, 1><<<grid, 256>>>(act_ptr, w1T_ptr, b1,
                                                nullptr, nullptr, hid_ptr, NN, HID, HD);
    }

    // 6. GEMM3: out(fp32) = hidden(fp16) @ W2 + b2
    {
        dim3 grid((NN + 127) / 128, MOUT / 128);
        gemm_f16_kernel<2, 0, 0><<<grid, 256>>>(hid_ptr, w2T_ptr, b2,
                                                nullptr, nullptr, out, NN, MOUT, HID);
    }
}

// round 16
// speedup vs baseline: 1.2435x; 1.0497x over previous
#include <cuda_runtime.h>
#include <cuda_fp16.h>
#include <cuda_bf16.h>

#define NN 50000
#define NE 800000
#define IND 128
#define OUTD 64
#define HEADS 4
#define HD 256      // HEADS*OUTD
#define HID 256
#define MOUT 128
#define NBLK 49     // ceil(NN/1024)

// ---- scratch (device globals: allocation-free) ----
__device__ __half g_xh[(size_t)NN * IND];     // node_embeddings in fp16
__device__ __half g_h[(size_t)NN * HD];       // transformed features (fp16)
__device__ __half g_act[(size_t)NN * HD];     // relu(num/den): GEMM2 input (fp16)
__device__ __half g_hidden[(size_t)NN * HID]; // MLP hidden (fp16)
__device__ float g_s_src[NN * HEADS];
__device__ float g_s_dst[NN * HEADS];
// weights: fp16, pre-transposed to [N][K] (col-major B for m16n8k16)
__device__ __half g_WcT[HD * IND];
__device__ __half g_W1T[HID * HD];
__device__ __half g_W2T[MOUT * HID];
// CSR-by-dst build
__device__ int g_cnt[NN];
__device__ int g_off[NN + 1];
__device__ int g_pos[NN];
__device__ int g_esrc[NE];
__device__ int g_bsum[NBLK];

// ---- pack weights (fp16, transposed) ----
__global__ void pack_w_kernel(const float* __restrict__ Wn,
                              const float* __restrict__ W1,
                              const float* __restrict__ W2) {
    int i = blockIdx.x * blockDim.x + threadIdx.x;
    if (i < HD * IND) {          // WcT[j][c] = Wn[h, c, d], j = h*64+d
        int j = i / IND;
        int c = i % IND;
        int h = j >> 6;
        int d = j & 63;
        g_WcT[i] = __float2half_rn(Wn[h * (IND * OUTD) + c * OUTD + d]);
    }
    if (i < HID * HD) {          // W1T[n][k] = W1[k][n]
        int n = i / HD;
        int k = i % HD;
        g_W1T[i] = __float2half_rn(W1[k * HID + n]);
    }
    if (i < MOUT * HID) {        // W2T[n][k] = W2[k][n]
        int n = i / HID;
        int k = i % HID;
        g_W2T[i] = __float2half_rn(W2[k * MOUT + n]);
    }
}

// ---- convert node embeddings fp32 -> fp16 (4 per thread) ----
__global__ void convert_x_kernel(const float* __restrict__ x) {
    int i = blockIdx.x * blockDim.x + threadIdx.x;
    if (i < NN * IND / 4) {
        float4 v = ((const float4*)x)[i];
        uint2 o;
        ((__half2*)&o)[0] = __floats2half2_rn(v.x, v.y);
        ((__half2*)&o)[1] = __floats2half2_rn(v.z, v.w);
        ((uint2*)g_xh)[i] = o;
    }
}

// ---- histogram of dst ----
__global__ void hist_kernel(const int* __restrict__ dst) {
    int i = blockIdx.x * blockDim.x + threadIdx.x;
    if (i < NE) atomicAdd(&g_cnt[dst[i]], 1);
}

// ---- 2-phase scan: block sums, then per-block scan with inline top-scan ----
__global__ void scan_blocks_kernel() {
    __shared__ int wsum[32];
    int tid = threadIdx.x;
    int i = blockIdx.x * 1024 + tid;
    int v = (i < NN) ? g_cnt[i] : 0;
#pragma unroll
    for (int o = 16; o > 0; o >>= 1) v += __shfl_down_sync(0xffffffffu, v, o);
    if ((tid & 31) == 0) wsum[tid >> 5] = v;
    __syncthreads();
    if (tid < 32) {
        int s = wsum[tid];
#pragma unroll
        for (int o = 16; o > 0; o >>= 1) s += __shfl_down_sync(0xffffffffu, s, o);
        if (tid == 0) g_bsum[blockIdx.x] = s;
    }
}

__global__ void scan_final_kernel() {
    __shared__ int wsum[32];
    __shared__ int sb[64];            // inclusive prefix of block sums
    int tid = threadIdx.x;
    int lane = tid & 31;
    int wid = tid >> 5;

    // warp 0: inline scan of the 49 block sums (redundant per block, trivial cost)
    if (wid == 0) {
        int v0 = (lane < NBLK) ? g_bsum[lane] : 0;
        int v1 = (lane + 32 < NBLK) ? g_bsum[lane + 32] : 0;
#pragma unroll
        for (int o = 1; o < 32; o <<= 1) {
            int t = __shfl_up_sync(0xffffffffu, v0, o);
            if (lane >= o) v0 += t;
        }
        int tot0 = __shfl_sync(0xffffffffu, v0, 31);
#pragma unroll
        for (int o = 1; o < 32; o <<= 1) {
            int t = __shfl_up_sync(0xffffffffu, v1, o);
            if (lane >= o) v1 += t;
        }
        sb[lane] = v0;
        sb[lane + 32] = v1 + tot0;
    }
    __syncthreads();
    int boff = (blockIdx.x > 0) ? sb[blockIdx.x - 1] : 0;

    int i = blockIdx.x * 1024 + tid;
    int v = (i < NN) ? g_cnt[i] : 0;
    int x = v;
#pragma unroll
    for (int o = 1; o < 32; o <<= 1) {
        int t = __shfl_up_sync(0xffffffffu, x, o);
        if (lane >= o) x += t;
    }
    if (lane == 31) wsum[wid] = x;
    __syncthreads();
    if (wid == 0) {
        int s = wsum[lane];
#pragma unroll
        for (int o = 1; o < 32; o <<= 1) {
            int t = __shfl_up_sync(0xffffffffu, s, o);
            if (lane >= o) s += t;
        }
        wsum[lane] = s;
    }
    __syncthreads();
    int excl = x - v + ((wid > 0) ? wsum[wid - 1] : 0) + boff;
    if (i < NN) { g_off[i] = excl; g_pos[i] = excl; }
    if (blockIdx.x == 0 && tid == 0) g_off[NN] = NE;
}

// ---- scatter edges into dst-grouped order ----
__global__ void scatter_kernel(const int* __restrict__ src, const int* __restrict__ dst) {
    int i = blockIdx.x * blockDim.x + threadIdx.x;
    if (i < NE) {
        int d = dst[i];
        int p = atomicAdd(&g_pos[d], 1);
        g_esrc[p] = src[i];
    }
}

__device__ __forceinline__ void mma_f16(float& c0, float& c1, float& c2, float& c3,
                                        unsigned a0, unsigned a1, unsigned a2, unsigned a3,
                                        unsigned b0, unsigned b1) {
    asm volatile("mma.sync.aligned.m16n8k16.row.col.f32.f16.f16.f32 "
                 "{%0,%1,%2,%3}, {%4,%5,%6,%7}, {%8,%9}, {%0,%1,%2,%3};"
                 : "+f"(c0), "+f"(c1), "+f"(c2), "+f"(c3)
                 : "r"(a0), "r"(a1), "r"(a2), "r"(a3), "r"(b0), "r"(b1));
}

__device__ __forceinline__ void cp_async16(void* smem_dst, const void* gmem_src, bool valid) {
    unsigned saddr = (unsigned)__cvta_generic_to_shared(smem_dst);
    int sz = valid ? 16 : 0;
    asm volatile("cp.async.cg.shared.global [%0], [%1], 16, %2;"
                 :: "r"(saddr), "l"(gmem_src), "r"(sz));
}

// ---- fp16 tensor-core GEMM: cp.async 2-stage pipeline + LDSM frag loads ----
// C[M,N] = act(A @ BT^T + bias). A fp16 [M][K], BT fp16 [N][K].
// EPI 0: none. 1: +bias, relu. 2: +bias.
// SCORE 1: emit g_s_src/g_s_dst from fp32 accumulators (GEMM1 only).
// CHALF: C is fp16 (else fp32).
template<int EPI, int SCORE, int CHALF>
__global__ void __launch_bounds__(256, 2)
gemm_f16_kernel(const __half* __restrict__ A, const __half* __restrict__ BT,
                const float* __restrict__ bias,
                const float* __restrict__ asrc, const float* __restrict__ adst,
                void* __restrict__ Cv, int M, int N, int K)
{
    const int BM = 128, BN = 128, BK = 32;
    const int PAD = 40;                    // 80B row stride: conflict-free LDSM phases
    __shared__ __half As[2][BM * PAD];     // [m][k]
    __shared__ __half Bs[2][BN * PAD];     // [n][k]

    float*  Cf = (float*)Cv;
    __half* Ch = (__half*)Cv;

    int tid = threadIdx.x;
    int wid = tid >> 5;
    int lane = tid & 31;
    int grp = lane >> 2;
    int tig = lane & 3;

    int warp_m = (wid & 3) * 32;
    int warp_n = (wid >> 2) * 64;

    int m0 = blockIdx.x * BM;
    int n0 = blockIdx.y * BN;

    auto copy_tile = [&](int buf, int k0) {
#pragma unroll
        for (int j = 0; j < 2; j++) {
            int i = tid + j * 256;
            int row = i >> 2;
            int c8 = (i & 3) * 8;
            int gm = m0 + row;
            bool ok = gm < M;
            int gma = ok ? gm : (M - 1);
            cp_async16(&As[buf][row * PAD + c8], A + (size_t)gma * K + k0 + c8, ok);
        }
#pragma unroll
        for (int j = 0; j < 2; j++) {
            int i = tid + j * 256;
            int n = i >> 2;
            int c8 = (i & 3) * 8;
            cp_async16(&Bs[buf][n * PAD + c8], BT + (size_t)(n0 + n) * K + k0 + c8, true);
        }
        asm volatile("cp.async.commit_group;");
    };

    float acc[2][8][4];
#pragma unroll
    for (int i = 0; i < 2; i++)
#pragma unroll
        for (int j = 0; j < 8; j++)
#pragma unroll
            for (int q = 0; q < 4; q++) acc[i][j][q] = 0.0f;

    copy_tile(0, 0);   // prologue

    int buf = 0;
    for (int k0 = 0; k0 < K; k0 += BK) {
        asm volatile("cp.async.wait_group 0;");
        __syncthreads();                      // stage buf ready for all warps

        int kn = k0 + BK;
        if (kn < K) copy_tile(buf ^ 1, kn);   // overlaps with MMAs below

        // compute: 2 k-steps of m16n8k16, fragments via ldmatrix.x4
#pragma unroll
        for (int kk = 0; kk < BK; kk += 16) {
            unsigned af[2][4];
#pragma unroll
            for (int mt = 0; mt < 2; mt++) {
                int r = warp_m + mt * 16 + (lane & 15);
                int c = kk + (lane >> 4) * 8;
                unsigned addr = (unsigned)__cvta_generic_to_shared(&As[buf][r * PAD + c]);
                asm volatile("ldmatrix.sync.aligned.m8n8.x4.shared.b16 {%0,%1,%2,%3}, [%4];"
                             : "=r"(af[mt][0]), "=r"(af[mt][1]),
                               "=r"(af[mt][2]), "=r"(af[mt][3])
                             : "r"(addr));
            }
            unsigned bf[8][2];
#pragma unroll
            for (int nt2 = 0; nt2 < 4; nt2++) {
                int nr = warp_n + nt2 * 16 + (lane & 7) + ((lane >> 4) << 3);
                int c = kk + ((lane >> 3) & 1) * 8;
                unsigned addr = (unsigned)__cvta_generic_to_shared(&Bs[buf][nr * PAD + c]);
                unsigned t0, t1, t2, t3;
                asm volatile("ldmatrix.sync.aligned.m8n8.x4.shared.b16 {%0,%1,%2,%3}, [%4];"
                             : "=r"(t0), "=r"(t1), "=r"(t2), "=r"(t3)
                             : "r"(addr));
                bf[nt2 * 2][0] = t0; bf[nt2 * 2][1] = t1;
                bf[nt2 * 2 + 1][0] = t2; bf[nt2 * 2 + 1][1] = t3;
            }
#pragma unroll
            for (int nt = 0; nt < 8; nt++)
#pragma unroll
                for (int mt = 0; mt < 2; mt++)
                    mma_f16(acc[mt][nt][0], acc[mt][nt][1], acc[mt][nt][2], acc[mt][nt][3],
                            af[mt][0], af[mt][1], af[mt][2], af[mt][3],
                            bf[nt][0], bf[nt][1]);
        }
        __syncthreads();                      // all warps done reading buf
        buf ^= 1;
    }

    // --- epilogue ---
    int head = (n0 + warp_n) >> 6;   // warp tile spans exactly one head
#pragma unroll
    for (int mt = 0; mt < 2; mt++) {
#pragma unroll
        for (int half = 0; half < 2; half++) {
            int gm = m0 + warp_m + mt * 16 + grp + half * 8;
            if (gm >= M) continue;
            float ss = 0.0f, sd = 0.0f;
#pragma unroll
            for (int nt = 0; nt < 8; nt++) {
                int gn = n0 + warp_n + nt * 8 + tig * 2;
                float v0 = acc[mt][nt][half * 2 + 0];
                float v1 = acc[mt][nt][half * 2 + 1];
                if (EPI >= 1) { v0 += bias[gn]; v1 += bias[gn + 1]; }
                if (EPI == 1) { v0 = fmaxf(v0, 0.0f); v1 = fmaxf(v1, 0.0f); }
                if (SCORE) {
                    float2 a2 = *(const float2*)(asrc + gn);
                    float2 d2 = *(const float2*)(adst + gn);
                    ss += v0 * a2.x + v1 * a2.y;
                    sd += v0 * d2.x + v1 * d2.y;
                }
                if (CHALF) {
                    *(__half2*)(Ch + (size_t)gm * N + gn) = __floats2half2_rn(v0, v1);
                } else {
                    *(float2*)(Cf + (size_t)gm * N + gn) = make_float2(v0, v1);
                }
            }
            if (SCORE) {
                ss += __shfl_down_sync(0xffffffffu, ss, 2);
                ss += __shfl_down_sync(0xffffffffu, ss, 1);
                sd += __shfl_down_sync(0xffffffffu, sd, 2);
                sd += __shfl_down_sync(0xffffffffu, sd, 1);
                if (tig == 0) {
                    g_s_src[gm * HEADS + head] = ss;
                    g_s_dst[gm * HEADS + head] = sd;
                }
            }
        }
    }
}

// ---- gather kernel: one warp per dst node, CSR edges, fp16 h, fp32 accum ----
__global__ void gather_kernel() {
    int gw = (blockIdx.x * blockDim.x + threadIdx.x) >> 5;
    int lane = threadIdx.x & 31;
    if (gw >= NN) return;

    int beg = g_off[gw];
    int end = g_off[gw + 1];
    int head = lane >> 3;           // lane covers halves [lane*8, lane*8+8)

    float sdst = (lane < HEADS) ? g_s_dst[gw * HEADS + lane] : 0.0f;

    float acc[8];
#pragma unroll
    for (int q = 0; q < 8; q++) acc[q] = 0.0f;
    float den = 0.0f;

    for (int chunk = beg; chunk < end; chunk += 32) {
        int myE = (chunk + lane < end) ? g_esrc[chunk + lane] : 0;
        int cnt = min(32, end - chunk);
        for (int j = 0; j < cnt; j++) {
            int s = __shfl_sync(0xffffffffu, myE, j);
            float ex = 0.0f;
            if (lane < HEADS) {
                float e = g_s_src[s * HEADS + lane] + sdst;
                e = e > 0.0f ? e : 0.2f * e;
                ex = __expf(e);
                den += ex;
            }
            float exh = __shfl_sync(0xffffffffu, ex, head);
            uint4 v = ((const uint4*)(g_h + (size_t)s * HD))[lane];
            const __half2* hv = (const __half2*)&v;
#pragma unroll
            for (int q = 0; q < 4; q++) {
                float2 f = __half22float2(hv[q]);
                acc[q * 2]     = fmaf(exh, f.x, acc[q * 2]);
                acc[q * 2 + 1] = fmaf(exh, f.y, acc[q * 2 + 1]);
            }
        }
    }

    float denh = __shfl_sync(0xffffffffu, den, head);
    float inv = denh > 0.0f ? 1.0f / denh : 0.0f;

    uint4 outv;
    __half2* ov = (__half2*)&outv;
#pragma unroll
    for (int q = 0; q < 4; q++) {
        float x = fmaxf(acc[q * 2]     * inv, 0.0f);
        float y = fmaxf(acc[q * 2 + 1] * inv, 0.0f);
        ov[q] = __floats2half2_rn(x, y);
    }
    ((uint4*)(g_act + (size_t)gw * HD))[lane] = outv;
}

extern "C" void kernel_launch(void* const* d_in, const int* in_sizes, int n_in,
                              void* d_out, int out_size) {
    const float* node_emb = (const float*)d_in[0];
    const int*   src      = (const int*)d_in[1];
    const int*   dst      = (const int*)d_in[2];
    const float* W_n      = (const float*)d_in[3];
    const float* a_src    = (const float*)d_in[4];
    const float* a_dst    = (const float*)d_in[5];
    const float* W1       = (const float*)d_in[6];
    const float* b1       = (const float*)d_in[7];
    const float* W2       = (const float*)d_in[8];
    const float* b2       = (const float*)d_in[9];
    float* out = (float*)d_out;

    __half* xh_ptr;  cudaGetSymbolAddress((void**)&xh_ptr, g_xh);
    __half* h_ptr;   cudaGetSymbolAddress((void**)&h_ptr, g_h);
    __half* act_ptr; cudaGetSymbolAddress((void**)&act_ptr, g_act);
    __half* hid_ptr; cudaGetSymbolAddress((void**)&hid_ptr, g_hidden);
    __half* wcT_ptr; cudaGetSymbolAddress((void**)&wcT_ptr, g_WcT);
    __half* w1T_ptr; cudaGetSymbolAddress((void**)&w1T_ptr, g_W1T);
    __half* w2T_ptr; cudaGetSymbolAddress((void**)&w2T_ptr, g_W2T);
    int* cnt_ptr;    cudaGetSymbolAddress((void**)&cnt_ptr, g_cnt);

    // Fork a second stream so the CSR build (dst-only) overlaps the
    // feature path (pack -> convert -> GEMM1). Event fork/join is the
    // sanctioned way to bring an extra stream into a stream capture.
    cudaStream_t s2;
    cudaStreamCreateWithFlags(&s2, cudaStreamNonBlocking);
    cudaEvent_t evFork, evJoin;
    cudaEventCreateWithFlags(&evFork, cudaEventDisableTiming);
    cudaEventCreateWithFlags(&evJoin, cudaEventDisableTiming);

    cudaEventRecord(evFork, 0);
    cudaStreamWaitEvent(s2, evFork, 0);

    // ---- stream B: CSR-by-dst build ----
    cudaMemsetAsync(cnt_ptr, 0, NN * sizeof(int), s2);
    hist_kernel<<<(NE + 255) / 256, 256, 0, s2>>>(dst);
    scan_blocks_kernel<<<NBLK, 1024, 0, s2>>>();
    scan_final_kernel<<<NBLK, 1024, 0, s2>>>();
    scatter_kernel<<<(NE + 255) / 256, 256, 0, s2>>>(src, dst);
    cudaEventRecord(evJoin, s2);

    // ---- stream A (default): feature path ----
    pack_w_kernel<<<(HID * HD + 255) / 256, 256>>>(W_n, W1, W2);
    convert_x_kernel<<<(NN * IND / 4 + 255) / 256, 256>>>(node_emb);
    {
        dim3 grid((NN + 127) / 128, HD / 128);
        gemm_f16_kernel<0, 1, 1><<<grid, 256>>>(xh_ptr, wcT_ptr, nullptr,
                                                a_src, a_dst, h_ptr, NN, HD, IND);
    }

    // ---- join: gather needs h, scores, and the CSR ----
    cudaStreamWaitEvent(0, evJoin, 0);

    gather_kernel<<<(NN * 32 + 255) / 256, 256>>>();

    {
        dim3 grid((NN + 127) / 128, HID / 128);
        gemm_f16_kernel<1, 0, 1><<<grid, 256>>>(act_ptr, w1T_ptr, b1,
                                                nullptr, nullptr, hid_ptr, NN, HID, HD);
    }
    {
        dim3 grid((NN + 127) / 128, MOUT / 128);
        gemm_f16_kernel<2, 0, 0><<<grid, 256>>>(hid_ptr, w2T_ptr, b2,
                                                nullptr, nullptr, out, NN, MOUT, HID);
    }

    cudaEventDestroy(evFork);
    cudaEventDestroy(evJoin);
    cudaStreamDestroy(s2);
}

// round 17
// speedup vs baseline: 1.2600x; 1.0133x over previous
#include <cuda_runtime.h>
#include <cuda_fp16.h>
#include <cuda_bf16.h>

#define NN 50000
#define NE 800000
#define IND 128
#define OUTD 64
#define HEADS 4
#define HD 256      // HEADS*OUTD
#define HID 256
#define MOUT 128
#define NBLK 49     // ceil(NN/1024)

// ---- scratch (device globals: allocation-free) ----
__device__ __half g_xh[(size_t)NN * IND];     // node_embeddings in fp16
__device__ __half g_h[(size_t)NN * HD];       // transformed features (fp16)
__device__ __half g_act[(size_t)NN * HD];     // relu(num/den): GEMM2 input (fp16)
__device__ __half g_hidden[(size_t)NN * HID]; // MLP hidden (fp16)
__device__ float g_s_src[NN * HEADS];
__device__ float g_s_dst[NN * HEADS];
// weights: fp16, pre-transposed to [N][K] (col-major B for m16n8k16)
__device__ __half g_WcT[HD * IND];
__device__ __half g_W1T[HID * HD];
__device__ __half g_W2T[MOUT * HID];
// CSR-by-dst build
__device__ int g_cnt[NN];
__device__ int g_off[NN + 1];
__device__ int g_pos[NN];
__device__ int g_esrc[NE];
__device__ int g_bsum[NBLK];

// ---- pack weights (fp16, transposed) ----
__global__ void pack_w_kernel(const float* __restrict__ Wn,
                              const float* __restrict__ W1,
                              const float* __restrict__ W2) {
    int i = blockIdx.x * blockDim.x + threadIdx.x;
    if (i < HD * IND) {          // WcT[j][c] = Wn[h, c, d], j = h*64+d
        int j = i / IND;
        int c = i % IND;
        int h = j >> 6;
        int d = j & 63;
        g_WcT[i] = __float2half_rn(Wn[h * (IND * OUTD) + c * OUTD + d]);
    }
    if (i < HID * HD) {          // W1T[n][k] = W1[k][n]
        int n = i / HD;
        int k = i % HD;
        g_W1T[i] = __float2half_rn(W1[k * HID + n]);
    }
    if (i < MOUT * HID) {        // W2T[n][k] = W2[k][n]
        int n = i / HID;
        int k = i % HID;
        g_W2T[i] = __float2half_rn(W2[k * MOUT + n]);
    }
}

// ---- convert node embeddings fp32 -> fp16 (4 per thread) ----
__global__ void convert_x_kernel(const float* __restrict__ x) {
    int i = blockIdx.x * blockDim.x + threadIdx.x;
    if (i < NN * IND / 4) {
        float4 v = ((const float4*)x)[i];
        uint2 o;
        ((__half2*)&o)[0] = __floats2half2_rn(v.x, v.y);
        ((__half2*)&o)[1] = __floats2half2_rn(v.z, v.w);
        ((uint2*)g_xh)[i] = o;
    }
}

// ---- histogram of dst ----
__global__ void hist_kernel(const int* __restrict__ dst) {
    int i = blockIdx.x * blockDim.x + threadIdx.x;
    if (i < NE) atomicAdd(&g_cnt[dst[i]], 1);
}

// ---- 2-phase scan: block sums, then per-block scan with inline top-scan ----
__global__ void scan_blocks_kernel() {
    __shared__ int wsum[32];
    int tid = threadIdx.x;
    int i = blockIdx.x * 1024 + tid;
    int v = (i < NN) ? g_cnt[i] : 0;
#pragma unroll
    for (int o = 16; o > 0; o >>= 1) v += __shfl_down_sync(0xffffffffu, v, o);
    if ((tid & 31) == 0) wsum[tid >> 5] = v;
    __syncthreads();
    if (tid < 32) {
        int s = wsum[tid];
#pragma unroll
        for (int o = 16; o > 0; o >>= 1) s += __shfl_down_sync(0xffffffffu, s, o);
        if (tid == 0) g_bsum[blockIdx.x] = s;
    }
}

__global__ void scan_final_kernel() {
    __shared__ int wsum[32];
    __shared__ int sb[64];            // inclusive prefix of block sums
    int tid = threadIdx.x;
    int lane = tid & 31;
    int wid = tid >> 5;

    // warp 0: inline scan of the 49 block sums (redundant per block, trivial cost)
    if (wid == 0) {
        int v0 = (lane < NBLK) ? g_bsum[lane] : 0;
        int v1 = (lane + 32 < NBLK) ? g_bsum[lane + 32] : 0;
#pragma unroll
        for (int o = 1; o < 32; o <<= 1) {
            int t = __shfl_up_sync(0xffffffffu, v0, o);
            if (lane >= o) v0 += t;
        }
        int tot0 = __shfl_sync(0xffffffffu, v0, 31);
#pragma unroll
        for (int o = 1; o < 32; o <<= 1) {
            int t = __shfl_up_sync(0xffffffffu, v1, o);
            if (lane >= o) v1 += t;
        }
        sb[lane] = v0;
        sb[lane + 32] = v1 + tot0;
    }
    __syncthreads();
    int boff = (blockIdx.x > 0) ? sb[blockIdx.x - 1] : 0;

    int i = blockIdx.x * 1024 + tid;
    int v = (i < NN) ? g_cnt[i] : 0;
    int x = v;
#pragma unroll
    for (int o = 1; o < 32; o <<= 1) {
        int t = __shfl_up_sync(0xffffffffu, x, o);
        if (lane >= o) x += t;
    }
    if (lane == 31) wsum[wid] = x;
    __syncthreads();
    if (wid == 0) {
        int s = wsum[lane];
#pragma unroll
        for (int o = 1; o < 32; o <<= 1) {
            int t = __shfl_up_sync(0xffffffffu, s, o);
            if (lane >= o) s += t;
        }
        wsum[lane] = s;
    }
    __syncthreads();
    int excl = x - v + ((wid > 0) ? wsum[wid - 1] : 0) + boff;
    if (i < NN) { g_off[i] = excl; g_pos[i] = excl; }
    if (blockIdx.x == 0 && tid == 0) g_off[NN] = NE;
}

// ---- scatter edges into dst-grouped order ----
__global__ void scatter_kernel(const int* __restrict__ src, const int* __restrict__ dst) {
    int i = blockIdx.x * blockDim.x + threadIdx.x;
    if (i < NE) {
        int d = dst[i];
        int p = atomicAdd(&g_pos[d], 1);
        g_esrc[p] = src[i];
    }
}

__device__ __forceinline__ void mma_f16(float& c0, float& c1, float& c2, float& c3,
                                        unsigned a0, unsigned a1, unsigned a2, unsigned a3,
                                        unsigned b0, unsigned b1) {
    asm volatile("mma.sync.aligned.m16n8k16.row.col.f32.f16.f16.f32 "
                 "{%0,%1,%2,%3}, {%4,%5,%6,%7}, {%8,%9}, {%0,%1,%2,%3};"
                 : "+f"(c0), "+f"(c1), "+f"(c2), "+f"(c3)
                 : "r"(a0), "r"(a1), "r"(a2), "r"(a3), "r"(b0), "r"(b1));
}

__device__ __forceinline__ void cp_async16(void* smem_dst, const void* gmem_src, bool valid) {
    unsigned saddr = (unsigned)__cvta_generic_to_shared(smem_dst);
    int sz = valid ? 16 : 0;
    asm volatile("cp.async.cg.shared.global [%0], [%1], 16, %2;"
                 :: "r"(saddr), "l"(gmem_src), "r"(sz));
}

// ---- fp16 tensor-core GEMM: cp.async 2-stage pipeline + LDSM frag loads ----
// C[M,N] = act(A @ BT^T + bias). A fp16 [M][K], BT fp16 [N][K].
// EPI 0: none. 1: +bias, relu. 2: +bias.
// SCORE 1: emit g_s_src/g_s_dst from fp32 accumulators (GEMM1 only).
// CHALF: C is fp16 (else fp32).
template<int EPI, int SCORE, int CHALF>
__global__ void __launch_bounds__(256, 2)
gemm_f16_kernel(const __half* __restrict__ A, const __half* __restrict__ BT,
                const float* __restrict__ bias,
                const float* __restrict__ asrc, const float* __restrict__ adst,
                void* __restrict__ Cv, int M, int N, int K)
{
    const int BM = 128, BN = 128, BK = 32;
    const int PAD = 40;                    // 80B row stride: conflict-free LDSM phases
    __shared__ __half As[2][BM * PAD];     // [m][k]
    __shared__ __half Bs[2][BN * PAD];     // [n][k]

    float*  Cf = (float*)Cv;
    __half* Ch = (__half*)Cv;

    int tid = threadIdx.x;
    int wid = tid >> 5;
    int lane = tid & 31;
    int grp = lane >> 2;
    int tig = lane & 3;

    int warp_m = (wid & 3) * 32;
    int warp_n = (wid >> 2) * 64;

    int m0 = blockIdx.x * BM;
    int n0 = blockIdx.y * BN;

    auto copy_tile = [&](int buf, int k0) {
#pragma unroll
        for (int j = 0; j < 2; j++) {
            int i = tid + j * 256;
            int row = i >> 2;
            int c8 = (i & 3) * 8;
            int gm = m0 + row;
            bool ok = gm < M;
            int gma = ok ? gm : (M - 1);
            cp_async16(&As[buf][row * PAD + c8], A + (size_t)gma * K + k0 + c8, ok);
        }
#pragma unroll
        for (int j = 0; j < 2; j++) {
            int i = tid + j * 256;
            int n = i >> 2;
            int c8 = (i & 3) * 8;
            cp_async16(&Bs[buf][n * PAD + c8], BT + (size_t)(n0 + n) * K + k0 + c8, true);
        }
        asm volatile("cp.async.commit_group;");
    };

    float acc[2][8][4];
#pragma unroll
    for (int i = 0; i < 2; i++)
#pragma unroll
        for (int j = 0; j < 8; j++)
#pragma unroll
            for (int q = 0; q < 4; q++) acc[i][j][q] = 0.0f;

    copy_tile(0, 0);   // prologue

    int buf = 0;
    for (int k0 = 0; k0 < K; k0 += BK) {
        asm volatile("cp.async.wait_group 0;");
        __syncthreads();                      // stage buf ready for all warps

        int kn = k0 + BK;
        if (kn < K) copy_tile(buf ^ 1, kn);   // overlaps with MMAs below

        // compute: 2 k-steps of m16n8k16, fragments via ldmatrix.x4
#pragma unroll
        for (int kk = 0; kk < BK; kk += 16) {
            unsigned af[2][4];
#pragma unroll
            for (int mt = 0; mt < 2; mt++) {
                int r = warp_m + mt * 16 + (lane & 15);
                int c = kk + (lane >> 4) * 8;
                unsigned addr = (unsigned)__cvta_generic_to_shared(&As[buf][r * PAD + c]);
                asm volatile("ldmatrix.sync.aligned.m8n8.x4.shared.b16 {%0,%1,%2,%3}, [%4];"
                             : "=r"(af[mt][0]), "=r"(af[mt][1]),
                               "=r"(af[mt][2]), "=r"(af[mt][3])
                             : "r"(addr));
            }
            unsigned bf[8][2];
#pragma unroll
            for (int nt2 = 0; nt2 < 4; nt2++) {
                int nr = warp_n + nt2 * 16 + (lane & 7) + ((lane >> 4) << 3);
                int c = kk + ((lane >> 3) & 1) * 8;
                unsigned addr = (unsigned)__cvta_generic_to_shared(&Bs[buf][nr * PAD + c]);
                unsigned t0, t1, t2, t3;
                asm volatile("ldmatrix.sync.aligned.m8n8.x4.shared.b16 {%0,%1,%2,%3}, [%4];"
                             : "=r"(t0), "=r"(t1), "=r"(t2), "=r"(t3)
                             : "r"(addr));
                bf[nt2 * 2][0] = t0; bf[nt2 * 2][1] = t1;
                bf[nt2 * 2 + 1][0] = t2; bf[nt2 * 2 + 1][1] = t3;
            }
#pragma unroll
            for (int nt = 0; nt < 8; nt++)
#pragma unroll
                for (int mt = 0; mt < 2; mt++)
                    mma_f16(acc[mt][nt][0], acc[mt][nt][1], acc[mt][nt][2], acc[mt][nt][3],
                            af[mt][0], af[mt][1], af[mt][2], af[mt][3],
                            bf[nt][0], bf[nt][1]);
        }
        __syncthreads();                      // all warps done reading buf
        buf ^= 1;
    }

    // --- epilogue ---
    int head = (n0 + warp_n) >> 6;   // warp tile spans exactly one head
#pragma unroll
    for (int mt = 0; mt < 2; mt++) {
#pragma unroll
        for (int half = 0; half < 2; half++) {
            int gm = m0 + warp_m + mt * 16 + grp + half * 8;
            if (gm >= M) continue;
            float ss = 0.0f, sd = 0.0f;
#pragma unroll
            for (int nt = 0; nt < 8; nt++) {
                int gn = n0 + warp_n + nt * 8 + tig * 2;
                float v0 = acc[mt][nt][half * 2 + 0];
                float v1 = acc[mt][nt][half * 2 + 1];
                if (EPI >= 1) { v0 += bias[gn]; v1 += bias[gn + 1]; }
                if (EPI == 1) { v0 = fmaxf(v0, 0.0f); v1 = fmaxf(v1, 0.0f); }
                if (SCORE) {
                    float2 a2 = *(const float2*)(asrc + gn);
                    float2 d2 = *(const float2*)(adst + gn);
                    ss += v0 * a2.x + v1 * a2.y;
                    sd += v0 * d2.x + v1 * d2.y;
                }
                if (CHALF) {
                    *(__half2*)(Ch + (size_t)gm * N + gn) = __floats2half2_rn(v0, v1);
                } else {
                    *(float2*)(Cf + (size_t)gm * N + gn) = make_float2(v0, v1);
                }
            }
            if (SCORE) {
                ss += __shfl_down_sync(0xffffffffu, ss, 2);
                ss += __shfl_down_sync(0xffffffffu, ss, 1);
                sd += __shfl_down_sync(0xffffffffu, sd, 2);
                sd += __shfl_down_sync(0xffffffffu, sd, 1);
                if (tig == 0) {
                    g_s_src[gm * HEADS + head] = ss;
                    g_s_dst[gm * HEADS + head] = sd;
                }
            }
        }
    }
}

// ---- gather kernel: one warp per dst node, CSR edges, fp16 h, fp32 accum ----
// Unrolled by 2: both row loads + both score loads issued before any consumer
// to double per-warp MLP (latency-bound per R16 ncu: 6.8 TB/s < NAT LTS cap).
__global__ void gather_kernel() {
    int gw = (blockIdx.x * blockDim.x + threadIdx.x) >> 5;
    int lane = threadIdx.x & 31;
    if (gw >= NN) return;

    int beg = g_off[gw];
    int end = g_off[gw + 1];
    int head = lane >> 3;           // lane covers halves [lane*8, lane*8+8)

    float sdst = (lane < HEADS) ? g_s_dst[gw * HEADS + lane] : 0.0f;

    float acc[8];
#pragma unroll
    for (int q = 0; q < 8; q++) acc[q] = 0.0f;
    float den = 0.0f;

    for (int chunk = beg; chunk < end; chunk += 32) {
        int myE = (chunk + lane < end) ? g_esrc[chunk + lane] : 0;
        int cnt = min(32, end - chunk);
        int j = 0;
        for (; j + 2 <= cnt; j += 2) {
            int s0 = __shfl_sync(0xffffffffu, myE, j);
            int s1 = __shfl_sync(0xffffffffu, myE, j + 1);
            // issue all 4 loads (2 rows + 2 scores) before any consumer
            uint4 v0 = ((const uint4*)(g_h + (size_t)s0 * HD))[lane];
            uint4 v1 = ((const uint4*)(g_h + (size_t)s1 * HD))[lane];
            float ex0 = 0.0f, ex1 = 0.0f;
            if (lane < HEADS) {
                float e0 = g_s_src[s0 * HEADS + lane] + sdst;
                float e1 = g_s_src[s1 * HEADS + lane] + sdst;
                e0 = e0 > 0.0f ? e0 : 0.2f * e0;
                e1 = e1 > 0.0f ? e1 : 0.2f * e1;
                ex0 = __expf(e0);
                ex1 = __expf(e1);
                den += ex0 + ex1;
            }
            float exh0 = __shfl_sync(0xffffffffu, ex0, head);
            float exh1 = __shfl_sync(0xffffffffu, ex1, head);
            const __half2* hv0 = (const __half2*)&v0;
            const __half2* hv1 = (const __half2*)&v1;
#pragma unroll
            for (int q = 0; q < 4; q++) {
                float2 f0 = __half22float2(hv0[q]);
                acc[q * 2]     = fmaf(exh0, f0.x, acc[q * 2]);
                acc[q * 2 + 1] = fmaf(exh0, f0.y, acc[q * 2 + 1]);
            }
#pragma unroll
            for (int q = 0; q < 4; q++) {
                float2 f1 = __half22float2(hv1[q]);
                acc[q * 2]     = fmaf(exh1, f1.x, acc[q * 2]);
                acc[q * 2 + 1] = fmaf(exh1, f1.y, acc[q * 2 + 1]);
            }
        }
        if (j < cnt) {                    // odd tail
            int s = __shfl_sync(0xffffffffu, myE, j);
            uint4 v = ((const uint4*)(g_h + (size_t)s * HD))[lane];
            float ex = 0.0f;
            if (lane < HEADS) {
                float e = g_s_src[s * HEADS + lane] + sdst;
                e = e > 0.0f ? e : 0.2f * e;
                ex = __expf(e);
                den += ex;
            }
            float exh = __shfl_sync(0xffffffffu, ex, head);
            const __half2* hv = (const __half2*)&v;
#pragma unroll
            for (int q = 0; q < 4; q++) {
                float2 f = __half22float2(hv[q]);
                acc[q * 2]     = fmaf(exh, f.x, acc[q * 2]);
                acc[q * 2 + 1] = fmaf(exh, f.y, acc[q * 2 + 1]);
            }
        }
    }

    float denh = __shfl_sync(0xffffffffu, den, head);
    float inv = denh > 0.0f ? 1.0f / denh : 0.0f;

    uint4 outv;
    __half2* ov = (__half2*)&outv;
#pragma unroll
    for (int q = 0; q < 4; q++) {
        float x = fmaxf(acc[q * 2]     * inv, 0.0f);
        float y = fmaxf(acc[q * 2 + 1] * inv, 0.0f);
        ov[q] = __floats2half2_rn(x, y);
    }
    ((uint4*)(g_act + (size_t)gw * HD))[lane] = outv;
}

extern "C" void kernel_launch(void* const* d_in, const int* in_sizes, int n_in,
                              void* d_out, int out_size) {
    const float* node_emb = (const float*)d_in[0];
    const int*   src      = (const int*)d_in[1];
    const int*   dst      = (const int*)d_in[2];
    const float* W_n      = (const float*)d_in[3];
    const float* a_src    = (const float*)d_in[4];
    const float* a_dst    = (const float*)d_in[5];
    const float* W1       = (const float*)d_in[6];
    const float* b1       = (const float*)d_in[7];
    const float* W2       = (const float*)d_in[8];
    const float* b2       = (const float*)d_in[9];
    float* out = (float*)d_out;

    __half* xh_ptr;  cudaGetSymbolAddress((void**)&xh_ptr, g_xh);
    __half* h_ptr;   cudaGetSymbolAddress((void**)&h_ptr, g_h);
    __half* act_ptr; cudaGetSymbolAddress((void**)&act_ptr, g_act);
    __half* hid_ptr; cudaGetSymbolAddress((void**)&hid_ptr, g_hidden);
    __half* wcT_ptr; cudaGetSymbolAddress((void**)&wcT_ptr, g_WcT);
    __half* w1T_ptr; cudaGetSymbolAddress((void**)&w1T_ptr, g_W1T);
    __half* w2T_ptr; cudaGetSymbolAddress((void**)&w2T_ptr, g_W2T);
    int* cnt_ptr;    cudaGetSymbolAddress((void**)&cnt_ptr, g_cnt);

    // Fork a second stream so the CSR build (dst-only) overlaps the
    // feature path (pack -> convert -> GEMM1).
    cudaStream_t s2;
    cudaStreamCreateWithFlags(&s2, cudaStreamNonBlocking);
    cudaEvent_t evFork, evJoin;
    cudaEventCreateWithFlags(&evFork, cudaEventDisableTiming);
    cudaEventCreateWithFlags(&evJoin, cudaEventDisableTiming);

    cudaEventRecord(evFork, 0);
    cudaStreamWaitEvent(s2, evFork, 0);

    // ---- stream B: CSR-by-dst build ----
    cudaMemsetAsync(cnt_ptr, 0, NN * sizeof(int), s2);
    hist_kernel<<<(NE + 255) / 256, 256, 0, s2>>>(dst);
    scan_blocks_kernel<<<NBLK, 1024, 0, s2>>>();
    scan_final_kernel<<<NBLK, 1024, 0, s2>>>();
    scatter_kernel<<<(NE + 255) / 256, 256, 0, s2>>>(src, dst);
    cudaEventRecord(evJoin, s2);

    // ---- stream A (default): feature path ----
    pack_w_kernel<<<(HID * HD + 255) / 256, 256>>>(W_n, W1, W2);
    convert_x_kernel<<<(NN * IND / 4 + 255) / 256, 256>>>(node_emb);
    {
        dim3 grid((NN + 127) / 128, HD / 128);
        gemm_f16_kernel<0, 1, 1><<<grid, 256>>>(xh_ptr, wcT_ptr, nullptr,
                                                a_src, a_dst, h_ptr, NN, HD, IND);
    }

    // ---- join: gather needs h, scores, and the CSR ----
    cudaStreamWaitEvent(0, evJoin, 0);

    gather_kernel<<<(NN * 32 + 255) / 256, 256>>>();

    {
        dim3 grid((NN + 127) / 128, HID / 128);
        gemm_f16_kernel<1, 0, 1><<<grid, 256>>>(act_ptr, w1T_ptr, b1,
                                                nullptr, nullptr, hid_ptr, NN, HID, HD);
    }
    {
        dim3 grid((NN + 127) / 128, MOUT / 128);
        gemm_f16_kernel<2, 0, 0><<<grid, 256>>>(hid_ptr, w2T_ptr, b2,
                                                nullptr, nullptr, out, NN, MOUT, HID);
    }

    cudaEventDestroy(evFork);
    cudaEventDestroy(evJoin);
    cudaStreamDestroy(s2);
}